// round 11
// baseline (speedup 1.0000x reference)
#include <cuda_runtime.h>
#include <cuda_fp16.h>
#include <math.h>
#include <stdint.h>

#define NL 4
#define NB 2
#define NS 1024
#define ND 1024
#define NH 16
#define NDH 64
#define NTOK (NB*NS)        // 2048
#define ATT_SCALE 0.125f
#define LN_EPS 1e-5f

typedef unsigned short u16;

// ---------------- scratch (static device globals: alloc-free) ----------------
__device__ float g_x    [NTOK*ND];
__device__ float g_tmp  [NTOK*ND];
__device__ float g_adapt[ND];

// split fp16 weights, grouped by TYPE (contiguous across layers)
#define WTOT 67108864ULL
#define OFF_P1 0ULL
#define OFF_P2 2097152ULL
#define OFF_Q1 4194304ULL
#define OFF_Q2 16777216ULL
#define OFF_O  29360128ULL
#define OFF_M1 33554432ULL
#define OFF_M2 50331648ULL
__device__ u16 g_wh [WTOT];
__device__ u16 g_wl [WTOT];
__device__ u16 g_hh [NTOK*ND],       g_hl [NTOK*ND];          // LN out
__device__ u16 g_x12h[2*NTOK*ND],    g_x12l[2*NTOK*ND];       // x1p|x2p (batched)
__device__ u16 g_q12h[2*NTOK*3*ND],  g_q12l[2*NTOK*3*ND];     // qkv1|qkv2 (batched)
__device__ u16 g_vah[32*NS*NDH],     g_val[32*NS*NDH];        // vavg TRANSPOSED [z][d][k]
__device__ u16 g_ph [NTOK*ND],       g_pl [NTOK*ND];          // attn out
__device__ u16 g_mh [NTOK*4*ND],     g_ml [NTOK*4*ND];        // gelu out

// ---------------- helpers ----------------
__device__ __forceinline__ uint32_t smem_u32(const void* p) {
    uint32_t a;
    asm("{ .reg .u64 t; cvta.to.shared.u64 t, %1; cvt.u32.u64 %0, t; }" : "=r"(a) : "l"(p));
    return a;
}
__device__ __forceinline__ void splitw(float v, u16& h, u16& l) {
    __half hh = __float2half_rn(v);
    h = __half_as_ushort(hh);
    l = __half_as_ushort(__float2half_rn(v - __half2float(hh)));
}
__device__ __forceinline__ void split2(float x, float y, uint32_t& hi, uint32_t& lo) {
    u16 hx, lx, hy, ly;
    splitw(x, hx, lx); splitw(y, hy, ly);
    hi = (uint32_t)hx | ((uint32_t)hy << 16);
    lo = (uint32_t)lx | ((uint32_t)ly << 16);
}
__device__ __forceinline__ float joinw(u16 h, u16 l) {
    return __half2float(__ushort_as_half(h)) + __half2float(__ushort_as_half(l));
}
__device__ __forceinline__ void mma16(float* c, const uint32_t* a, const uint32_t* b) {
    asm volatile(
        "mma.sync.aligned.m16n8k16.row.col.f32.f16.f16.f32 "
        "{%0,%1,%2,%3},{%4,%5,%6,%7},{%8,%9},{%0,%1,%2,%3};\n"
        : "+f"(c[0]), "+f"(c[1]), "+f"(c[2]), "+f"(c[3])
        : "r"(a[0]), "r"(a[1]), "r"(a[2]), "r"(a[3]), "r"(b[0]), "r"(b[1]));
}
__device__ __forceinline__ void ldsm4t(uint32_t* r, uint32_t addr) {
    asm volatile("ldmatrix.sync.aligned.m8n8.x4.trans.shared.b16 {%0,%1,%2,%3}, [%4];"
        : "=r"(r[0]), "=r"(r[1]), "=r"(r[2]), "=r"(r[3]) : "r"(addr));
}
__device__ __forceinline__ void cpa16(uint32_t dst, const void* src) {
    asm volatile("cp.async.cg.shared.global [%0], [%1], 16;" :: "r"(dst), "l"(src));
}
__device__ __forceinline__ void cpacommit() { asm volatile("cp.async.commit_group;"); }
template<int N> __device__ __forceinline__ void cpawait() {
    asm volatile("cp.async.wait_group %0;" :: "n"(N));
}

template<bool MAXRED>
__device__ __forceinline__ float blk_reduce(float v, float* red) {
    int t = threadIdx.x;  // 256 threads
    red[t] = v; __syncthreads();
    #pragma unroll
    for (int o = 128; o > 0; o >>= 1) {
        if (t < o) red[t] = MAXRED ? fmaxf(red[t], red[t + o]) : (red[t] + red[t + o]);
        __syncthreads();
    }
    float r = red[0];
    __syncthreads();
    return r;
}

// ---------------- tiny kernels ----------------
__global__ void copy_kernel(const float* __restrict__ in, float* __restrict__ out, int n) {
    int i = blockIdx.x * 256 + threadIdx.x;
    if (i < n) out[i] = in[i];
}

__global__ void wsplit_kernel(const float* __restrict__ w, u16* __restrict__ h,
                              u16* __restrict__ l, size_t n) {
    for (size_t i = ((size_t)blockIdx.x * 256 + threadIdx.x) * 4; i < n;
         i += (size_t)gridDim.x * 1024) {
        float4 v = *(const float4*)(w + i);
        u16 h0,l0,h1,l1,h2,l2,h3,l3;
        splitw(v.x,h0,l0); splitw(v.y,h1,l1); splitw(v.z,h2,l2); splitw(v.w,h3,l3);
        *(uint2*)(h + i) = make_uint2((uint32_t)h0 | ((uint32_t)h1<<16),
                                      (uint32_t)h2 | ((uint32_t)h3<<16));
        *(uint2*)(l + i) = make_uint2((uint32_t)l0 | ((uint32_t)l1<<16),
                                      (uint32_t)l2 | ((uint32_t)l3<<16));
    }
}

__global__ void adapt_kernel(const float* __restrict__ U, const float* __restrict__ V,
                             const float* __restrict__ sigma, float* __restrict__ adapt) {
    __shared__ float red[256];
    __shared__ float vsum[4];
    int t = threadIdx.x;
    for (int r = 0; r < 4; r++) {
        float s = 0.f;
        for (int j = t; j < ND; j += 256) s += V[r * ND + j];
        s = blk_reduce<false>(s, red);
        if (t == 0) vsum[r] = s;
        __syncthreads();
    }
    float sg = sigma[0];
    for (int i = t; i < ND; i += 256) {
        float a = 0.f;
        #pragma unroll
        for (int r = 0; r < 4; r++) a += U[i * 4 + r] * vsum[r];
        adapt[i] = a * sg;
    }
}

template<bool ADD_ADAPT, bool RES, bool SPLIT>
__global__ void ln_kernel(const float* __restrict__ in, const float* __restrict__ g,
                          const float* __restrict__ b, const float* __restrict__ adapt,
                          const float* __restrict__ res, float* __restrict__ out,
                          u16* __restrict__ oh, u16* __restrict__ ol) {
    __shared__ float red[256];
    int row = blockIdx.x, t = threadIdx.x;
    const float* rin = in + (size_t)row * ND;
    float v[4];
    #pragma unroll
    for (int i = 0; i < 4; i++) v[i] = rin[t + i * 256];
    float s = v[0] + v[1] + v[2] + v[3];
    float mean = blk_reduce<false>(s, red) * (1.0f / ND);
    float sq = 0.f;
    #pragma unroll
    for (int i = 0; i < 4; i++) { float d = v[i] - mean; sq += d * d; }
    float var = blk_reduce<false>(sq, red) * (1.0f / ND);
    float inv = rsqrtf(var + LN_EPS);
    #pragma unroll
    for (int i = 0; i < 4; i++) {
        int c = t + i * 256;
        float o = (v[i] - mean) * inv * g[c] + b[c];
        if (ADD_ADAPT) o += adapt[c];
        if (RES)       o += res[(size_t)row * ND + c];
        size_t idx = (size_t)row * ND + c;
        if (SPLIT) { u16 hh, ll; splitw(o, hh, ll); oh[idx] = hh; ol[idx] = ll; }
        else out[idx] = o;
    }
}

// vavg transposed: out[z][d][k] = 0.5*(v1+v2)
__global__ void vavg_t_kernel(const u16* __restrict__ q1h, const u16* __restrict__ q1l,
                              const u16* __restrict__ q2h, const u16* __restrict__ q2l,
                              u16* __restrict__ oh, u16* __restrict__ ol) {
    __shared__ float tile[64][65];
    int z = blockIdx.y, b = z >> 4, h = z & 15;
    int kt = blockIdx.x * 64;
    int t = threadIdx.x;
    for (int idx = t; idx < 4096; idx += 256) {
        int k = idx >> 6, d = idx & 63;
        size_t src = (size_t)(b * NS + kt + k) * 3072 + 2048 + h * 64 + d;
        tile[k][d] = 0.5f * (joinw(q1h[src], q1l[src]) + joinw(q2h[src], q2l[src]));
    }
    __syncthreads();
    for (int idx = t; idx < 4096; idx += 256) {
        int d = idx >> 6, k = idx & 63;
        float v = tile[k][d];
        u16 hh, ll; splitw(v, hh, ll);
        size_t dst = ((size_t)z * 64 + d) * 1024 + kt + k;
        oh[dst] = hh; ol[dst] = ll;
    }
}

// ---------------- fused dual-softmax-diff flash attention ----------------
__global__ void __launch_bounds__(256, 1) flash_kernel(
    const u16* __restrict__ q1h, const u16* __restrict__ q1l,
    const u16* __restrict__ q2h, const u16* __restrict__ q2l,
    const u16* __restrict__ vth, const u16* __restrict__ vtl,
    u16* __restrict__ oh, u16* __restrict__ ol)
{
    constexpr int QP = 72, KP = 72;
    constexpr int QSZ = 128 * QP;
    constexpr int KSZ = 64 * KP;
    constexpr int STGH = 6 * KSZ;
    extern __shared__ u16 sm[];
    const uint32_t smbase = smem_u32(sm);

    const int t = threadIdx.x, w = t >> 5, lane = t & 31;
    const int g = lane >> 2, th = lane & 3;
    const int z = blockIdx.y, b = z >> 4, h = z & 15;
    const int q0 = blockIdx.x * 128;
    const int wm = w * 16;

    for (int c = t; c < 128 * 8; c += 256) {
        int row = c >> 3, c8 = (c & 7) * 8;
        size_t gidx = (size_t)(b * NS + q0 + row) * 3072 + h * 64 + c8;
        uint32_t doff = (uint32_t)(row * QP + c8) * 2;
        cpa16(smbase + (0*QSZ)*2 + doff, q1h + gidx);
        cpa16(smbase + (1*QSZ)*2 + doff, q1l + gidx);
        cpa16(smbase + (2*QSZ)*2 + doff, q2h + gidx);
        cpa16(smbase + (3*QSZ)*2 + doff, q2l + gidx);
    }
    cpacommit();

    auto issue_kv = [&](int kt, int s) {
        const uint32_t sb = smbase + (uint32_t)(4*QSZ + s*STGH) * 2;
        for (int c = t; c < 64 * 8; c += 256) {
            int row = c >> 3, c8 = (c & 7) * 8;
            size_t kidx = (size_t)(b * NS + kt + row) * 3072 + 1024 + h * 64 + c8;
            uint32_t doff = (uint32_t)(row * KP + c8) * 2;
            cpa16(sb + (0*KSZ)*2 + doff, q1h + kidx);
            cpa16(sb + (1*KSZ)*2 + doff, q1l + kidx);
            cpa16(sb + (2*KSZ)*2 + doff, q2h + kidx);
            cpa16(sb + (3*KSZ)*2 + doff, q2l + kidx);
            size_t vidx = ((size_t)z * 64 + row) * 1024 + kt + c8;
            cpa16(sb + (4*KSZ)*2 + doff, vth + vidx);
            cpa16(sb + (5*KSZ)*2 + doff, vtl + vidx);
        }
        cpacommit();
    };
    issue_kv(0, 0);

    float O1[8][4] = {}, O2[8][4] = {};
    float m1[2] = {-1e30f, -1e30f}, l1[2] = {0.f, 0.f};
    float m2[2] = {-1e30f, -1e30f}, l2[2] = {0.f, 0.f};

    for (int kt_i = 0; kt_i < 16; kt_i++) {
        cpawait<0>();
        __syncthreads();
        if (kt_i + 1 < 16) issue_kv((kt_i + 1) * 64, (kt_i + 1) & 1);

        const int s = kt_i & 1;
        const u16* stg = sm + 4*QSZ + s*STGH;
        const u16* Vh_s = stg + 4*KSZ;
        const u16* Vl_s = stg + 5*KSZ;

        #pragma unroll
        for (int br = 0; br < 2; br++) {
            const u16* Qh_s = sm + (br*2 + 0)*QSZ;
            const u16* Ql_s = sm + (br*2 + 1)*QSZ;
            const u16* Kh_s = stg + (br*2 + 0)*KSZ;
            const u16* Kl_s = stg + (br*2 + 1)*KSZ;
            float (*O)[4] = br ? O2 : O1;
            float* m = br ? m2 : m1;
            float* l = br ? l2 : l1;

            float c[8][4] = {};
            #pragma unroll
            for (int ks = 0; ks < 4; ks++) {
                int ko = ks * 16;
                uint32_t bh[8][2], bl[8][2];
                #pragma unroll
                for (int ni = 0; ni < 8; ni++) {
                    int n = ni * 8 + g;
                    bh[ni][0] = *(const uint32_t*)&Kh_s[n * KP + ko + 2*th];
                    bh[ni][1] = *(const uint32_t*)&Kh_s[n * KP + ko + 8 + 2*th];
                    bl[ni][0] = *(const uint32_t*)&Kl_s[n * KP + ko + 2*th];
                    bl[ni][1] = *(const uint32_t*)&Kl_s[n * KP + ko + 8 + 2*th];
                }
                uint32_t af[4];
                af[0] = *(const uint32_t*)&Qh_s[(wm + g    ) * QP + ko + 2*th];
                af[1] = *(const uint32_t*)&Qh_s[(wm + g + 8) * QP + ko + 2*th];
                af[2] = *(const uint32_t*)&Qh_s[(wm + g    ) * QP + ko + 8 + 2*th];
                af[3] = *(const uint32_t*)&Qh_s[(wm + g + 8) * QP + ko + 8 + 2*th];
                #pragma unroll
                for (int ni = 0; ni < 8; ni++) {
                    mma16(c[ni], af, bh[ni]);
                    mma16(c[ni], af, bl[ni]);
                }
                af[0] = *(const uint32_t*)&Ql_s[(wm + g    ) * QP + ko + 2*th];
                af[1] = *(const uint32_t*)&Ql_s[(wm + g + 8) * QP + ko + 2*th];
                af[2] = *(const uint32_t*)&Ql_s[(wm + g    ) * QP + ko + 8 + 2*th];
                af[3] = *(const uint32_t*)&Ql_s[(wm + g + 8) * QP + ko + 8 + 2*th];
                #pragma unroll
                for (int ni = 0; ni < 8; ni++)
                    mma16(c[ni], af, bh[ni]);
            }
            #pragma unroll
            for (int ni = 0; ni < 8; ni++) {
                c[ni][0] *= ATT_SCALE; c[ni][1] *= ATT_SCALE;
                c[ni][2] *= ATT_SCALE; c[ni][3] *= ATT_SCALE;
            }

            float mx0 = -1e30f, mx1 = -1e30f;
            #pragma unroll
            for (int ni = 0; ni < 8; ni++) {
                mx0 = fmaxf(mx0, fmaxf(c[ni][0], c[ni][1]));
                mx1 = fmaxf(mx1, fmaxf(c[ni][2], c[ni][3]));
            }
            mx0 = fmaxf(mx0, __shfl_xor_sync(0xffffffffu, mx0, 1));
            mx0 = fmaxf(mx0, __shfl_xor_sync(0xffffffffu, mx0, 2));
            mx1 = fmaxf(mx1, __shfl_xor_sync(0xffffffffu, mx1, 1));
            mx1 = fmaxf(mx1, __shfl_xor_sync(0xffffffffu, mx1, 2));
            float mn0 = fmaxf(m[0], mx0), mn1 = fmaxf(m[1], mx1);
            float a0 = __expf(m[0] - mn0), a1 = __expf(m[1] - mn1);
            m[0] = mn0; m[1] = mn1;

            uint32_t pfh[4][4], pfl[4][4];
            float s0 = 0.f, s1 = 0.f;
            #pragma unroll
            for (int ni = 0; ni < 8; ni++) {
                float p0 = __expf(c[ni][0] - mn0);
                float p1 = __expf(c[ni][1] - mn0);
                float p2 = __expf(c[ni][2] - mn1);
                float p3 = __expf(c[ni][3] - mn1);
                s0 += p0 + p1; s1 += p2 + p3;
                uint32_t h01, l01, h23, l23;
                split2(p0, p1, h01, l01);
                split2(p2, p3, h23, l23);
                int j = ni >> 1, sl = (ni & 1) * 2;
                pfh[j][sl]   = h01; pfl[j][sl]   = l01;
                pfh[j][sl+1] = h23; pfl[j][sl+1] = l23;
            }
            s0 += __shfl_xor_sync(0xffffffffu, s0, 1);
            s0 += __shfl_xor_sync(0xffffffffu, s0, 2);
            s1 += __shfl_xor_sync(0xffffffffu, s1, 1);
            s1 += __shfl_xor_sync(0xffffffffu, s1, 2);
            l[0] = l[0] * a0 + s0;
            l[1] = l[1] * a1 + s1;

            #pragma unroll
            for (int ni = 0; ni < 8; ni++) {
                O[ni][0] *= a0; O[ni][1] *= a0;
                O[ni][2] *= a1; O[ni][3] *= a1;
            }

            #pragma unroll
            for (int j = 0; j < 4; j++) {
                int ko = j * 16;
                #pragma unroll
                for (int nd = 0; nd < 8; nd++) {
                    int n = nd * 8 + g;
                    uint32_t vb[2], vbl[2];
                    vb[0]  = *(const uint32_t*)&Vh_s[n * KP + ko + 2*th];
                    vb[1]  = *(const uint32_t*)&Vh_s[n * KP + ko + 8 + 2*th];
                    vbl[0] = *(const uint32_t*)&Vl_s[n * KP + ko + 2*th];
                    vbl[1] = *(const uint32_t*)&Vl_s[n * KP + ko + 8 + 2*th];
                    mma16(O[nd], pfh[j], vb);
                    mma16(O[nd], pfh[j], vbl);
                    mma16(O[nd], pfl[j], vb);
                }
            }
        }
    }

    float i10 = 1.f / l1[0], i11 = 1.f / l1[1];
    float i20 = 1.f / l2[0], i21 = 1.f / l2[1];
    #pragma unroll
    for (int ni = 0; ni < 8; ni++) {
        int col = h * 64 + ni * 8 + th * 2;
        size_t r0 = (size_t)(b * NS + q0 + wm + g    ) * ND + col;
        size_t r1 = (size_t)(b * NS + q0 + wm + g + 8) * ND + col;
        float v0 = O1[ni][0] * i10 - O2[ni][0] * i20;
        float v1 = O1[ni][1] * i10 - O2[ni][1] * i20;
        float v2 = O1[ni][2] * i11 - O2[ni][2] * i21;
        float v3 = O1[ni][3] * i11 - O2[ni][3] * i21;
        uint32_t H01, L01, H23, L23;
        split2(v0, v1, H01, L01);
        split2(v2, v3, H23, L23);
        *(uint32_t*)&oh[r0] = H01; *(uint32_t*)&ol[r0] = L01;
        *(uint32_t*)&oh[r1] = H23; *(uint32_t*)&ol[r1] = L23;
    }
}

// ---------------- split-fp16 mma.sync GEMM (R6-proven), NSTG-stage pipeline --
// bias2: when non-null, z&15 selects bias (batched branch pairs).
#define OUT_F32 0
#define OUT_SPLIT 1

template<int BN, bool TRANSB, bool GELU, bool RES, int OUTM, int NSTG>
__global__ void __launch_bounds__(256, 2) mma_gemm(
    const u16* __restrict__ Ahg, const u16* __restrict__ Alg, int lda, long long aO, long long aI,
    const u16* __restrict__ Bhg, const u16* __restrict__ Blg, int ldb, long long bO, long long bI,
    const float* __restrict__ bias, const float* __restrict__ bias2,
    const float* __restrict__ res,
    float* __restrict__ Cf, u16* __restrict__ Chi, u16* __restrict__ Clo,
    int ldc, long long cO, long long cI, int K, float alpha)
{
    constexpr int AP = 40;
    constexpr int ASZ = 128 * AP;
    constexpr int BROWS = TRANSB ? BN : 32;
    constexpr int BP = TRANSB ? 40 : (BN + 8);
    constexpr int BSZ = BROWS * BP;
    constexpr int STG = 2 * ASZ + 2 * BSZ;
    extern __shared__ u16 sm[];

    const int t = threadIdx.x;
    const int w = t >> 5, lane = t & 31;
    const int g = lane >> 2, th = lane & 3;
    const int m0 = blockIdx.y * 128, n0 = blockIdx.x * BN;
    const int z = blockIdx.z;
    const long long offA = (long long)(z >> 4) * aO + (long long)(z & 15) * aI;
    const long long offB = (long long)(z >> 4) * bO + (long long)(z & 15) * bI;
    const long long offC = (long long)(z >> 4) * cO + (long long)(z & 15) * cI;
    const u16* Ah_g = Ahg + offA;
    const u16* Al_g = Alg + offA;
    const u16* Bh_g = Bhg + offB;
    const u16* Bl_g = Blg + offB;
    const float* bsel = ((z & 15) && bias2) ? bias2 : bias;

    constexpr int MFRAG = (BN == 128) ? 4 : 2;
    const int wm = (BN == 128) ? ((w >> 2) * 64) : ((w >> 1) * 32);
    const int wn = (BN == 128) ? ((w & 3) * 32) : ((w & 1) * 32);

    const int lrow = (lane & 7) + ((lane & 8) ? 8 : 0);
    const int lcol = (lane & 16) ? 8 : 0;
    const uint32_t smbase = smem_u32(sm);

    float acc[MFRAG][4][4] = {};

    auto issue = [&](int kt, int s) {
        const uint32_t ah = smbase + (uint32_t)(s * STG) * 2;
        const uint32_t al = ah + ASZ * 2;
        const uint32_t bh = al + ASZ * 2;
        const uint32_t bl = bh + BSZ * 2;
        #pragma unroll
        for (int c = t; c < 512; c += 256) {
            int row = c >> 2, k8 = (c & 3) * 8;
            size_t gidx = (size_t)(m0 + row) * lda + kt + k8;
            uint32_t doff = (uint32_t)(row * AP + k8) * 2;
            cpa16(ah + doff, Ah_g + gidx);
            cpa16(al + doff, Al_g + gidx);
        }
        if (TRANSB) {
            #pragma unroll
            for (int c = t; c < BN * 4; c += 256) {
                int row = c >> 2, k8 = (c & 3) * 8;
                size_t gidx = (size_t)(n0 + row) * ldb + kt + k8;
                uint32_t doff = (uint32_t)(row * BP + k8) * 2;
                cpa16(bh + doff, Bh_g + gidx);
                cpa16(bl + doff, Bl_g + gidx);
            }
        } else {
            constexpr int CPR = BN / 8;
            #pragma unroll
            for (int c = t; c < 32 * CPR; c += 256) {
                int row = c / CPR, n8 = (c % CPR) * 8;
                size_t gidx = (size_t)(kt + row) * ldb + n0 + n8;
                uint32_t doff = (uint32_t)(row * BP + n8) * 2;
                cpa16(bh + doff, Bh_g + gidx);
                cpa16(bl + doff, Bl_g + gidx);
            }
        }
        cpacommit();
    };

    const int tiles = K >> 5;
    #pragma unroll
    for (int p = 0; p < NSTG - 1 && p < tiles; p++) issue(p << 5, p % NSTG);

    for (int i = 0; i < tiles; i++) {
        cpawait<NSTG - 2>();
        __syncthreads();
        {
            int nx = i + NSTG - 1;
            if (nx < tiles) issue(nx << 5, nx % NSTG);
        }
        const int s = i % NSTG;
        const u16* Ah_s = sm + s * STG;
        const u16* Al_s = Ah_s + ASZ;
        const u16* Bh_s = Al_s + ASZ;
        const u16* Bl_s = Bh_s + BSZ;
        const uint32_t bh_base = smbase + (uint32_t)(s * STG + 2 * ASZ) * 2;
        const uint32_t bl_base = bh_base + BSZ * 2;

        #pragma unroll
        for (int ks = 0; ks < 2; ks++) {
            int ko = ks * 16;
            uint32_t bhf[4][2], blf[4][2];
            if (TRANSB) {
                #pragma unroll
                for (int ni = 0; ni < 4; ni++) {
                    int n = wn + ni * 8 + g;
                    bhf[ni][0] = *(const uint32_t*)&Bh_s[n * BP + ko + 2 * th];
                    bhf[ni][1] = *(const uint32_t*)&Bh_s[n * BP + ko + 8 + 2 * th];
                    blf[ni][0] = *(const uint32_t*)&Bl_s[n * BP + ko + 2 * th];
                    blf[ni][1] = *(const uint32_t*)&Bl_s[n * BP + ko + 8 + 2 * th];
                }
            } else {
                #pragma unroll
                for (int pr = 0; pr < 2; pr++) {
                    uint32_t off = (uint32_t)(((ko + lrow) * BP + wn + pr * 16 + lcol) * 2);
                    uint32_t r[4];
                    ldsm4t(r, bh_base + off);
                    bhf[pr*2][0]=r[0]; bhf[pr*2][1]=r[1]; bhf[pr*2+1][0]=r[2]; bhf[pr*2+1][1]=r[3];
                    ldsm4t(r, bl_base + off);
                    blf[pr*2][0]=r[0]; blf[pr*2][1]=r[1]; blf[pr*2+1][0]=r[2]; blf[pr*2+1][1]=r[3];
                }
            }
            uint32_t af[MFRAG][4];
            #pragma unroll
            for (int mi = 0; mi < MFRAG; mi++) {
                int mr = wm + mi * 16 + g;
                af[mi][0] = *(const uint32_t*)&Ah_s[(mr    ) * AP + ko + 2 * th];
                af[mi][1] = *(const uint32_t*)&Ah_s[(mr + 8) * AP + ko + 2 * th];
                af[mi][2] = *(const uint32_t*)&Ah_s[(mr    ) * AP + ko + 8 + 2 * th];
                af[mi][3] = *(const uint32_t*)&Ah_s[(mr + 8) * AP + ko + 8 + 2 * th];
            }
            #pragma unroll
            for (int mi = 0; mi < MFRAG; mi++)
                #pragma unroll
                for (int ni = 0; ni < 4; ni++) {
                    mma16(acc[mi][ni], af[mi], bhf[ni]);
                    mma16(acc[mi][ni], af[mi], blf[ni]);
                }
            #pragma unroll
            for (int mi = 0; mi < MFRAG; mi++) {
                int mr = wm + mi * 16 + g;
                af[mi][0] = *(const uint32_t*)&Al_s[(mr    ) * AP + ko + 2 * th];
                af[mi][1] = *(const uint32_t*)&Al_s[(mr + 8) * AP + ko + 2 * th];
                af[mi][2] = *(const uint32_t*)&Al_s[(mr    ) * AP + ko + 8 + 2 * th];
                af[mi][3] = *(const uint32_t*)&Al_s[(mr + 8) * AP + ko + 8 + 2 * th];
            }
            #pragma unroll
            for (int mi = 0; mi < MFRAG; mi++)
                #pragma unroll
                for (int ni = 0; ni < 4; ni++)
                    mma16(acc[mi][ni], af[mi], bhf[ni]);
        }
    }

    // ---- epilogue ----
    #pragma unroll
    for (int mi = 0; mi < MFRAG; mi++) {
        #pragma unroll
        for (int ni = 0; ni < 4; ni++) {
            int col = n0 + wn + ni * 8 + th * 2;
            #pragma unroll
            for (int half = 0; half < 2; half++) {
                int row = m0 + wm + mi * 16 + g + half * 8;
                float v0 = acc[mi][ni][half * 2 + 0] * alpha;
                float v1 = acc[mi][ni][half * 2 + 1] * alpha;
                if (bsel) { v0 += bsel[col]; v1 += bsel[col + 1]; }
                if (RES) {
                    v0 += res[(size_t)row * ldc + col];
                    v1 += res[(size_t)row * ldc + col + 1];
                }
                if (GELU) {
                    v0 = 0.5f * v0 * (1.0f + erff(v0 * 0.70710678118654752f));
                    v1 = 0.5f * v1 * (1.0f + erff(v1 * 0.70710678118654752f));
                }
                size_t idx = offC + (size_t)row * ldc + col;
                if (OUTM == OUT_SPLIT) {
                    u16 h0, l0, h1, l1;
                    splitw(v0, h0, l0); splitw(v1, h1, l1);
                    *(uint32_t*)&Chi[idx] = (uint32_t)h0 | ((uint32_t)h1 << 16);
                    *(uint32_t*)&Clo[idx] = (uint32_t)l0 | ((uint32_t)l1 << 16);
                } else {
                    *(float2*)&Cf[idx] = make_float2(v0, v1);
                }
            }
        }
    }
}

// ---------------- host orchestration ----------------
extern "C" void kernel_launch(void* const* d_in, const int* in_sizes, int n_in,
                              void* d_out, int out_size) {
    (void)in_sizes; (void)n_in; (void)out_size;
    const float* x     = (const float*)d_in[0];
    const float* sigma = (const float*)d_in[1];
    const float* U     = (const float*)d_in[2];
    const float* V     = (const float*)d_in[3];
    const float* Wqkv1 = (const float*)d_in[4];
    const float* Wqkv2 = (const float*)d_in[5];
    const float* Wp1   = (const float*)d_in[6];
    const float* bp1   = (const float*)d_in[7];
    const float* Wp2   = (const float*)d_in[8];
    const float* bp2   = (const float*)d_in[9];
    const float* Wo    = (const float*)d_in[10];
    const float* bo    = (const float*)d_in[11];
    const float* gO    = (const float*)d_in[12];
    const float* bO    = (const float*)d_in[13];
    const float* g1    = (const float*)d_in[14];
    const float* b1    = (const float*)d_in[15];
    const float* g2    = (const float*)d_in[16];
    const float* b2    = (const float*)d_in[17];
    const float* Wm1   = (const float*)d_in[18];
    const float* bm1   = (const float*)d_in[19];
    const float* Wm2   = (const float*)d_in[20];
    const float* bm2   = (const float*)d_in[21];
    const float* gf    = (const float*)d_in[22];
    const float* bf    = (const float*)d_in[23];

    float *px, *ptmp, *pad;
    u16 *wh, *wl, *hh, *hl, *x12h, *x12l, *q12h, *q12l;
    u16 *vah, *val, *ph_, *pl_, *mh, *ml;
    cudaGetSymbolAddress((void**)&px,   g_x);
    cudaGetSymbolAddress((void**)&ptmp, g_tmp);
    cudaGetSymbolAddress((void**)&pad,  g_adapt);
    cudaGetSymbolAddress((void**)&wh,   g_wh);
    cudaGetSymbolAddress((void**)&wl,   g_wl);
    cudaGetSymbolAddress((void**)&hh,   g_hh);
    cudaGetSymbolAddress((void**)&hl,   g_hl);
    cudaGetSymbolAddress((void**)&x12h, g_x12h);
    cudaGetSymbolAddress((void**)&x12l, g_x12l);
    cudaGetSymbolAddress((void**)&q12h, g_q12h);
    cudaGetSymbolAddress((void**)&q12l, g_q12l);
    cudaGetSymbolAddress((void**)&vah,  g_vah);
    cudaGetSymbolAddress((void**)&val,  g_val);
    cudaGetSymbolAddress((void**)&ph_,  g_ph);
    cudaGetSymbolAddress((void**)&pl_,  g_pl);
    cudaGetSymbolAddress((void**)&mh,   g_mh);
    cudaGetSymbolAddress((void**)&ml,   g_ml);

    const long long QS = (long long)NTOK * 3 * ND;   // q12 branch stride
    const long long XS = (long long)NTOK * ND;       // x12 branch stride
    u16 *q1h = q12h, *q1l = q12l, *q2h = q12h + QS, *q2l = q12l + QS;

    // dynamic smem sizes (bytes)
    const int SM_B64_S3  = 3 * (2*128*40 + 2*32*72)  * 2;   // 89088
    const int SM_FLASH   = (4*128*72 + 2*6*64*72) * 2;      // 184320
    cudaFuncSetAttribute((const void*)mma_gemm<64,false,false,false,OUT_SPLIT,3>, cudaFuncAttributeMaxDynamicSharedMemorySize, SM_B64_S3);
    cudaFuncSetAttribute((const void*)mma_gemm<64,false,false,false,OUT_F32,  3>, cudaFuncAttributeMaxDynamicSharedMemorySize, SM_B64_S3);
    cudaFuncSetAttribute((const void*)mma_gemm<64,false,false,true, OUT_F32,  3>, cudaFuncAttributeMaxDynamicSharedMemorySize, SM_B64_S3);
    cudaFuncSetAttribute((const void*)mma_gemm<64,false,true, false,OUT_SPLIT,3>, cudaFuncAttributeMaxDynamicSharedMemorySize, SM_B64_S3);
    cudaFuncSetAttribute((const void*)flash_kernel, cudaFuncAttributeMaxDynamicSharedMemorySize, SM_FLASH);

    copy_kernel<<<NTOK * ND / 256, 256>>>(x, px, NTOK * ND);

    // pre-split weights, grouped by type (7 launches)
    wsplit_kernel<<<2048, 256>>>(Wp1,   wh + OFF_P1, wl + OFF_P1, (size_t)NL*512*ND);
    wsplit_kernel<<<2048, 256>>>(Wp2,   wh + OFF_P2, wl + OFF_P2, (size_t)NL*512*ND);
    wsplit_kernel<<<4096, 256>>>(Wqkv1, wh + OFF_Q1, wl + OFF_Q1, (size_t)NL*ND*3*ND);
    wsplit_kernel<<<4096, 256>>>(Wqkv2, wh + OFF_Q2, wl + OFF_Q2, (size_t)NL*ND*3*ND);
    wsplit_kernel<<<2048, 256>>>(Wo,    wh + OFF_O,  wl + OFF_O,  (size_t)NL*ND*ND);
    wsplit_kernel<<<4096, 256>>>(Wm1,   wh + OFF_M1, wl + OFF_M1, (size_t)NL*ND*4*ND);
    wsplit_kernel<<<4096, 256>>>(Wm2,   wh + OFF_M2, wl + OFF_M2, (size_t)NL*4*ND*ND);

    for (int l = 0; l < NL; l++) {
        const size_t oP1 = OFF_P1 + (size_t)l*512*ND;
        const size_t oQ1 = OFF_Q1 + (size_t)l*ND*3*ND;
        const size_t oO  = OFF_O  + (size_t)l*ND*ND;
        const size_t oM1 = OFF_M1 + (size_t)l*ND*4*ND;
        const size_t oM2 = OFF_M2 + (size_t)l*4*ND*ND;

        adapt_kernel<<<1, 256>>>(U + (size_t)l * ND * 4, V + (size_t)l * 4 * ND, sigma + l, pad);
        ln_kernel<true, false, true><<<NTOK, 256>>>(px, g1 + l*ND, b1 + l*ND, pad, nullptr, nullptr, hh, hl);

        // x1p & x2p batched: z=0 -> a[:, :512]@Wp1+bp1; z=1 -> a[:, 512:]@Wp2+bp2
        mma_gemm<64,false,false,false,OUT_SPLIT,3><<<dim3(16,16,2), 256, SM_B64_S3>>>(
            hh, hl, ND, 0, 512,
            wh+oP1, wl+oP1, ND, 0, (long long)(OFF_P2 - OFF_P1),
            bp1 + l*ND, bp2 + l*ND, nullptr,
            nullptr, x12h, x12l, ND, 0, XS, 512, 1.0f);

        // qkv batched: z=0 -> x1p@Wqkv1; z=1 -> x2p@Wqkv2  (BN=64, 2 CTAs/SM)
        mma_gemm<64,false,false,false,OUT_SPLIT,3><<<dim3(48,16,2), 256, SM_B64_S3>>>(
            x12h, x12l, ND, 0, XS,
            wh+oQ1, wl+oQ1, 3*ND, 0, (long long)(OFF_Q2 - OFF_Q1),
            nullptr, nullptr, nullptr,
            nullptr, q12h, q12l, 3*ND, 0, QS, ND, 1.0f);

        // fused attention
        vavg_t_kernel<<<dim3(16, 32), 256>>>(q1h, q1l, q2h, q2l, vah, val);
        flash_kernel<<<dim3(8, 32), 256, SM_FLASH>>>(q1h, q1l, q2h, q2l, vah, val, ph_, pl_);

        // out proj + post-LN + residual
        mma_gemm<64,false,false,false,OUT_F32,3><<<dim3(16,16), 256, SM_B64_S3>>>(
            ph_, pl_, ND, 0, 0, wh+oO, wl+oO, ND, 0, 0,
            bo + l*ND, nullptr, nullptr, ptmp, nullptr, nullptr, ND, 0, 0, ND, 1.0f);
        ln_kernel<false, true, false><<<NTOK, 256>>>(ptmp, gO + l*ND, bO + l*ND, nullptr, px, px, nullptr, nullptr);

        // MLP (Wm1 now BN=64 for 2 CTAs/SM)
        ln_kernel<false, false, true><<<NTOK, 256>>>(px, g2 + l*ND, b2 + l*ND, nullptr, nullptr, nullptr, hh, hl);
        mma_gemm<64,false,true,false,OUT_SPLIT,3><<<dim3(64,16), 256, SM_B64_S3>>>(
            hh, hl, ND, 0, 0, wh+oM1, wl+oM1, 4*ND, 0, 0,
            bm1 + (size_t)l*4*ND, nullptr, nullptr, nullptr, mh, ml, 4*ND, 0, 0, ND, 1.0f);
        mma_gemm<64,false,false,true,OUT_F32,3><<<dim3(16,16), 256, SM_B64_S3>>>(
            mh, ml, 4*ND, 0, 0, wh+oM2, wl+oM2, ND, 0, 0,
            bm2 + l*ND, nullptr, px, px, nullptr, nullptr, ND, 0, 0, 4*ND, 1.0f);
    }

    ln_kernel<false, false, false><<<NTOK, 256>>>(px, gf, bf, nullptr, nullptr, (float*)d_out, nullptr, nullptr);
}

// round 12
// speedup vs baseline: 1.0252x; 1.0252x over previous
#include <cuda_runtime.h>
#include <cuda_fp16.h>
#include <math.h>
#include <stdint.h>

#define NL 4
#define NB 2
#define NS 1024
#define ND 1024
#define NH 16
#define NDH 64
#define NTOK (NB*NS)        // 2048
#define ATT_SCALE 0.125f
#define LN_EPS 1e-5f

typedef unsigned short u16;

// ---------------- scratch (static device globals: alloc-free) ----------------
__device__ float g_x    [NTOK*ND];
__device__ float g_tmp  [NTOK*ND];
__device__ float g_adapt[ND];

// split fp16 weights, grouped by TYPE (contiguous across layers)
#define WTOT 67108864ULL
#define OFF_P1 0ULL
#define OFF_P2 2097152ULL
#define OFF_Q1 4194304ULL
#define OFF_Q2 16777216ULL
#define OFF_O  29360128ULL
#define OFF_M1 33554432ULL
#define OFF_M2 50331648ULL
__device__ u16 g_wh [WTOT];
__device__ u16 g_wl [WTOT];
__device__ u16 g_hh [NTOK*ND],       g_hl [NTOK*ND];          // LN out
__device__ u16 g_x12h[2*NTOK*ND],    g_x12l[2*NTOK*ND];       // x1p|x2p (batched)
__device__ u16 g_q12h[2*NTOK*3*ND],  g_q12l[2*NTOK*3*ND];     // qkv1|qkv2 (batched)
__device__ u16 g_vah[32*NS*NDH],     g_val[32*NS*NDH];        // vavg TRANSPOSED [z][d][k]
__device__ u16 g_ph [NTOK*ND],       g_pl [NTOK*ND];          // attn out
__device__ u16 g_mh [NTOK*4*ND],     g_ml [NTOK*4*ND];        // gelu out

// ---------------- helpers ----------------
__device__ __forceinline__ uint32_t smem_u32(const void* p) {
    uint32_t a;
    asm("{ .reg .u64 t; cvta.to.shared.u64 t, %1; cvt.u32.u64 %0, t; }" : "=r"(a) : "l"(p));
    return a;
}
__device__ __forceinline__ void splitw(float v, u16& h, u16& l) {
    __half hh = __float2half_rn(v);
    h = __half_as_ushort(hh);
    l = __half_as_ushort(__float2half_rn(v - __half2float(hh)));
}
__device__ __forceinline__ void split2(float x, float y, uint32_t& hi, uint32_t& lo) {
    u16 hx, lx, hy, ly;
    splitw(x, hx, lx); splitw(y, hy, ly);
    hi = (uint32_t)hx | ((uint32_t)hy << 16);
    lo = (uint32_t)lx | ((uint32_t)ly << 16);
}
__device__ __forceinline__ float joinw(u16 h, u16 l) {
    return __half2float(__ushort_as_half(h)) + __half2float(__ushort_as_half(l));
}
__device__ __forceinline__ void mma16(float* c, const uint32_t* a, const uint32_t* b) {
    asm volatile(
        "mma.sync.aligned.m16n8k16.row.col.f32.f16.f16.f32 "
        "{%0,%1,%2,%3},{%4,%5,%6,%7},{%8,%9},{%0,%1,%2,%3};\n"
        : "+f"(c[0]), "+f"(c[1]), "+f"(c[2]), "+f"(c[3])
        : "r"(a[0]), "r"(a[1]), "r"(a[2]), "r"(a[3]), "r"(b[0]), "r"(b[1]));
}
__device__ __forceinline__ void ldsm4t(uint32_t* r, uint32_t addr) {
    asm volatile("ldmatrix.sync.aligned.m8n8.x4.trans.shared.b16 {%0,%1,%2,%3}, [%4];"
        : "=r"(r[0]), "=r"(r[1]), "=r"(r[2]), "=r"(r[3]) : "r"(addr));
}
__device__ __forceinline__ void cpa16(uint32_t dst, const void* src) {
    asm volatile("cp.async.cg.shared.global [%0], [%1], 16;" :: "r"(dst), "l"(src));
}
__device__ __forceinline__ void cpacommit() { asm volatile("cp.async.commit_group;"); }
template<int N> __device__ __forceinline__ void cpawait() {
    asm volatile("cp.async.wait_group %0;" :: "n"(N));
}

template<bool MAXRED>
__device__ __forceinline__ float blk_reduce(float v, float* red) {
    int t = threadIdx.x;  // 256 threads
    red[t] = v; __syncthreads();
    #pragma unroll
    for (int o = 128; o > 0; o >>= 1) {
        if (t < o) red[t] = MAXRED ? fmaxf(red[t], red[t + o]) : (red[t] + red[t + o]);
        __syncthreads();
    }
    float r = red[0];
    __syncthreads();
    return r;
}

// ---------------- tiny kernels ----------------
__global__ void copy_kernel(const float* __restrict__ in, float* __restrict__ out, int n) {
    int i = blockIdx.x * 256 + threadIdx.x;
    if (i < n) out[i] = in[i];
}

__global__ void wsplit_kernel(const float* __restrict__ w, u16* __restrict__ h,
                              u16* __restrict__ l, size_t n) {
    for (size_t i = ((size_t)blockIdx.x * 256 + threadIdx.x) * 4; i < n;
         i += (size_t)gridDim.x * 1024) {
        float4 v = *(const float4*)(w + i);
        u16 h0,l0,h1,l1,h2,l2,h3,l3;
        splitw(v.x,h0,l0); splitw(v.y,h1,l1); splitw(v.z,h2,l2); splitw(v.w,h3,l3);
        *(uint2*)(h + i) = make_uint2((uint32_t)h0 | ((uint32_t)h1<<16),
                                      (uint32_t)h2 | ((uint32_t)h3<<16));
        *(uint2*)(l + i) = make_uint2((uint32_t)l0 | ((uint32_t)l1<<16),
                                      (uint32_t)l2 | ((uint32_t)l3<<16));
    }
}

__global__ void adapt_kernel(const float* __restrict__ U, const float* __restrict__ V,
                             const float* __restrict__ sigma, float* __restrict__ adapt) {
    __shared__ float red[256];
    __shared__ float vsum[4];
    int t = threadIdx.x;
    for (int r = 0; r < 4; r++) {
        float s = 0.f;
        for (int j = t; j < ND; j += 256) s += V[r * ND + j];
        s = blk_reduce<false>(s, red);
        if (t == 0) vsum[r] = s;
        __syncthreads();
    }
    float sg = sigma[0];
    for (int i = t; i < ND; i += 256) {
        float a = 0.f;
        #pragma unroll
        for (int r = 0; r < 4; r++) a += U[i * 4 + r] * vsum[r];
        adapt[i] = a * sg;
    }
}

template<bool ADD_ADAPT, bool RES, bool SPLIT>
__global__ void ln_kernel(const float* __restrict__ in, const float* __restrict__ g,
                          const float* __restrict__ b, const float* __restrict__ adapt,
                          const float* __restrict__ res, float* __restrict__ out,
                          u16* __restrict__ oh, u16* __restrict__ ol) {
    __shared__ float red[256];
    int row = blockIdx.x, t = threadIdx.x;
    const float* rin = in + (size_t)row * ND;
    float v[4];
    #pragma unroll
    for (int i = 0; i < 4; i++) v[i] = rin[t + i * 256];
    float s = v[0] + v[1] + v[2] + v[3];
    float mean = blk_reduce<false>(s, red) * (1.0f / ND);
    float sq = 0.f;
    #pragma unroll
    for (int i = 0; i < 4; i++) { float d = v[i] - mean; sq += d * d; }
    float var = blk_reduce<false>(sq, red) * (1.0f / ND);
    float inv = rsqrtf(var + LN_EPS);
    #pragma unroll
    for (int i = 0; i < 4; i++) {
        int c = t + i * 256;
        float o = (v[i] - mean) * inv * g[c] + b[c];
        if (ADD_ADAPT) o += adapt[c];
        if (RES)       o += res[(size_t)row * ND + c];
        size_t idx = (size_t)row * ND + c;
        if (SPLIT) { u16 hh, ll; splitw(o, hh, ll); oh[idx] = hh; ol[idx] = ll; }
        else out[idx] = o;
    }
}

// vavg transposed: out[z][d][k] = 0.5*(v1+v2)
__global__ void vavg_t_kernel(const u16* __restrict__ q1h, const u16* __restrict__ q1l,
                              const u16* __restrict__ q2h, const u16* __restrict__ q2l,
                              u16* __restrict__ oh, u16* __restrict__ ol) {
    __shared__ float tile[64][65];
    int z = blockIdx.y, b = z >> 4, h = z & 15;
    int kt = blockIdx.x * 64;
    int t = threadIdx.x;
    for (int idx = t; idx < 4096; idx += 256) {
        int k = idx >> 6, d = idx & 63;
        size_t src = (size_t)(b * NS + kt + k) * 3072 + 2048 + h * 64 + d;
        tile[k][d] = 0.5f * (joinw(q1h[src], q1l[src]) + joinw(q2h[src], q2l[src]));
    }
    __syncthreads();
    for (int idx = t; idx < 4096; idx += 256) {
        int d = idx >> 6, k = idx & 63;
        float v = tile[k][d];
        u16 hh, ll; splitw(v, hh, ll);
        size_t dst = ((size_t)z * 64 + d) * 1024 + kt + k;
        oh[dst] = hh; ol[dst] = ll;
    }
}

// ---------------- fused dual-softmax-diff flash attention ----------------
__global__ void __launch_bounds__(256, 1) flash_kernel(
    const u16* __restrict__ q1h, const u16* __restrict__ q1l,
    const u16* __restrict__ q2h, const u16* __restrict__ q2l,
    const u16* __restrict__ vth, const u16* __restrict__ vtl,
    u16* __restrict__ oh, u16* __restrict__ ol)
{
    constexpr int QP = 72, KP = 72;
    constexpr int QSZ = 128 * QP;
    constexpr int KSZ = 64 * KP;
    constexpr int STGH = 6 * KSZ;
    extern __shared__ u16 sm[];
    const uint32_t smbase = smem_u32(sm);

    const int t = threadIdx.x, w = t >> 5, lane = t & 31;
    const int g = lane >> 2, th = lane & 3;
    const int z = blockIdx.y, b = z >> 4, h = z & 15;
    const int q0 = blockIdx.x * 128;
    const int wm = w * 16;

    for (int c = t; c < 128 * 8; c += 256) {
        int row = c >> 3, c8 = (c & 7) * 8;
        size_t gidx = (size_t)(b * NS + q0 + row) * 3072 + h * 64 + c8;
        uint32_t doff = (uint32_t)(row * QP + c8) * 2;
        cpa16(smbase + (0*QSZ)*2 + doff, q1h + gidx);
        cpa16(smbase + (1*QSZ)*2 + doff, q1l + gidx);
        cpa16(smbase + (2*QSZ)*2 + doff, q2h + gidx);
        cpa16(smbase + (3*QSZ)*2 + doff, q2l + gidx);
    }
    cpacommit();

    auto issue_kv = [&](int kt, int s) {
        const uint32_t sb = smbase + (uint32_t)(4*QSZ + s*STGH) * 2;
        for (int c = t; c < 64 * 8; c += 256) {
            int row = c >> 3, c8 = (c & 7) * 8;
            size_t kidx = (size_t)(b * NS + kt + row) * 3072 + 1024 + h * 64 + c8;
            uint32_t doff = (uint32_t)(row * KP + c8) * 2;
            cpa16(sb + (0*KSZ)*2 + doff, q1h + kidx);
            cpa16(sb + (1*KSZ)*2 + doff, q1l + kidx);
            cpa16(sb + (2*KSZ)*2 + doff, q2h + kidx);
            cpa16(sb + (3*KSZ)*2 + doff, q2l + kidx);
            size_t vidx = ((size_t)z * 64 + row) * 1024 + kt + c8;
            cpa16(sb + (4*KSZ)*2 + doff, vth + vidx);
            cpa16(sb + (5*KSZ)*2 + doff, vtl + vidx);
        }
        cpacommit();
    };
    issue_kv(0, 0);

    float O1[8][4] = {}, O2[8][4] = {};
    float m1[2] = {-1e30f, -1e30f}, l1[2] = {0.f, 0.f};
    float m2[2] = {-1e30f, -1e30f}, l2[2] = {0.f, 0.f};

    for (int kt_i = 0; kt_i < 16; kt_i++) {
        cpawait<0>();
        __syncthreads();
        if (kt_i + 1 < 16) issue_kv((kt_i + 1) * 64, (kt_i + 1) & 1);

        const int s = kt_i & 1;
        const u16* stg = sm + 4*QSZ + s*STGH;
        const u16* Vh_s = stg + 4*KSZ;
        const u16* Vl_s = stg + 5*KSZ;

        #pragma unroll
        for (int br = 0; br < 2; br++) {
            const u16* Qh_s = sm + (br*2 + 0)*QSZ;
            const u16* Ql_s = sm + (br*2 + 1)*QSZ;
            const u16* Kh_s = stg + (br*2 + 0)*KSZ;
            const u16* Kl_s = stg + (br*2 + 1)*KSZ;
            float (*O)[4] = br ? O2 : O1;
            float* m = br ? m2 : m1;
            float* l = br ? l2 : l1;

            float c[8][4] = {};
            #pragma unroll
            for (int ks = 0; ks < 4; ks++) {
                int ko = ks * 16;
                uint32_t bh[8][2], bl[8][2];
                #pragma unroll
                for (int ni = 0; ni < 8; ni++) {
                    int n = ni * 8 + g;
                    bh[ni][0] = *(const uint32_t*)&Kh_s[n * KP + ko + 2*th];
                    bh[ni][1] = *(const uint32_t*)&Kh_s[n * KP + ko + 8 + 2*th];
                    bl[ni][0] = *(const uint32_t*)&Kl_s[n * KP + ko + 2*th];
                    bl[ni][1] = *(const uint32_t*)&Kl_s[n * KP + ko + 8 + 2*th];
                }
                uint32_t af[4];
                af[0] = *(const uint32_t*)&Qh_s[(wm + g    ) * QP + ko + 2*th];
                af[1] = *(const uint32_t*)&Qh_s[(wm + g + 8) * QP + ko + 2*th];
                af[2] = *(const uint32_t*)&Qh_s[(wm + g    ) * QP + ko + 8 + 2*th];
                af[3] = *(const uint32_t*)&Qh_s[(wm + g + 8) * QP + ko + 8 + 2*th];
                #pragma unroll
                for (int ni = 0; ni < 8; ni++) {
                    mma16(c[ni], af, bh[ni]);
                    mma16(c[ni], af, bl[ni]);
                }
                af[0] = *(const uint32_t*)&Ql_s[(wm + g    ) * QP + ko + 2*th];
                af[1] = *(const uint32_t*)&Ql_s[(wm + g + 8) * QP + ko + 2*th];
                af[2] = *(const uint32_t*)&Ql_s[(wm + g    ) * QP + ko + 8 + 2*th];
                af[3] = *(const uint32_t*)&Ql_s[(wm + g + 8) * QP + ko + 8 + 2*th];
                #pragma unroll
                for (int ni = 0; ni < 8; ni++)
                    mma16(c[ni], af, bh[ni]);
            }
            #pragma unroll
            for (int ni = 0; ni < 8; ni++) {
                c[ni][0] *= ATT_SCALE; c[ni][1] *= ATT_SCALE;
                c[ni][2] *= ATT_SCALE; c[ni][3] *= ATT_SCALE;
            }

            float mx0 = -1e30f, mx1 = -1e30f;
            #pragma unroll
            for (int ni = 0; ni < 8; ni++) {
                mx0 = fmaxf(mx0, fmaxf(c[ni][0], c[ni][1]));
                mx1 = fmaxf(mx1, fmaxf(c[ni][2], c[ni][3]));
            }
            mx0 = fmaxf(mx0, __shfl_xor_sync(0xffffffffu, mx0, 1));
            mx0 = fmaxf(mx0, __shfl_xor_sync(0xffffffffu, mx0, 2));
            mx1 = fmaxf(mx1, __shfl_xor_sync(0xffffffffu, mx1, 1));
            mx1 = fmaxf(mx1, __shfl_xor_sync(0xffffffffu, mx1, 2));
            float mn0 = fmaxf(m[0], mx0), mn1 = fmaxf(m[1], mx1);
            float a0 = __expf(m[0] - mn0), a1 = __expf(m[1] - mn1);
            m[0] = mn0; m[1] = mn1;

            uint32_t pfh[4][4], pfl[4][4];
            float s0 = 0.f, s1 = 0.f;
            #pragma unroll
            for (int ni = 0; ni < 8; ni++) {
                float p0 = __expf(c[ni][0] - mn0);
                float p1 = __expf(c[ni][1] - mn0);
                float p2 = __expf(c[ni][2] - mn1);
                float p3 = __expf(c[ni][3] - mn1);
                s0 += p0 + p1; s1 += p2 + p3;
                uint32_t h01, l01, h23, l23;
                split2(p0, p1, h01, l01);
                split2(p2, p3, h23, l23);
                int j = ni >> 1, sl = (ni & 1) * 2;
                pfh[j][sl]   = h01; pfl[j][sl]   = l01;
                pfh[j][sl+1] = h23; pfl[j][sl+1] = l23;
            }
            s0 += __shfl_xor_sync(0xffffffffu, s0, 1);
            s0 += __shfl_xor_sync(0xffffffffu, s0, 2);
            s1 += __shfl_xor_sync(0xffffffffu, s1, 1);
            s1 += __shfl_xor_sync(0xffffffffu, s1, 2);
            l[0] = l[0] * a0 + s0;
            l[1] = l[1] * a1 + s1;

            #pragma unroll
            for (int ni = 0; ni < 8; ni++) {
                O[ni][0] *= a0; O[ni][1] *= a0;
                O[ni][2] *= a1; O[ni][3] *= a1;
            }

            #pragma unroll
            for (int j = 0; j < 4; j++) {
                int ko = j * 16;
                #pragma unroll
                for (int nd = 0; nd < 8; nd++) {
                    int n = nd * 8 + g;
                    uint32_t vb[2], vbl[2];
                    vb[0]  = *(const uint32_t*)&Vh_s[n * KP + ko + 2*th];
                    vb[1]  = *(const uint32_t*)&Vh_s[n * KP + ko + 8 + 2*th];
                    vbl[0] = *(const uint32_t*)&Vl_s[n * KP + ko + 2*th];
                    vbl[1] = *(const uint32_t*)&Vl_s[n * KP + ko + 8 + 2*th];
                    mma16(O[nd], pfh[j], vb);
                    mma16(O[nd], pfh[j], vbl);
                    mma16(O[nd], pfl[j], vb);
                }
            }
        }
    }

    float i10 = 1.f / l1[0], i11 = 1.f / l1[1];
    float i20 = 1.f / l2[0], i21 = 1.f / l2[1];
    #pragma unroll
    for (int ni = 0; ni < 8; ni++) {
        int col = h * 64 + ni * 8 + th * 2;
        size_t r0 = (size_t)(b * NS + q0 + wm + g    ) * ND + col;
        size_t r1 = (size_t)(b * NS + q0 + wm + g + 8) * ND + col;
        float v0 = O1[ni][0] * i10 - O2[ni][0] * i20;
        float v1 = O1[ni][1] * i10 - O2[ni][1] * i20;
        float v2 = O1[ni][2] * i11 - O2[ni][2] * i21;
        float v3 = O1[ni][3] * i11 - O2[ni][3] * i21;
        uint32_t H01, L01, H23, L23;
        split2(v0, v1, H01, L01);
        split2(v2, v3, H23, L23);
        *(uint32_t*)&oh[r0] = H01; *(uint32_t*)&ol[r0] = L01;
        *(uint32_t*)&oh[r1] = H23; *(uint32_t*)&ol[r1] = L23;
    }
}

// ---------------- split-fp16 mma.sync GEMM, NSTG-stage pipeline -------------
// bias2: when non-null, blockIdx.z&15 selects bias (batched branch pairs).
#define OUT_F32 0
#define OUT_SPLIT 1

template<int BN, bool TRANSB, bool GELU, bool RES, int OUTM, int NSTG>
__global__ void __launch_bounds__(256, 2) mma_gemm(
    const u16* __restrict__ Ahg, const u16* __restrict__ Alg, int lda, long long aO, long long aI,
    const u16* __restrict__ Bhg, const u16* __restrict__ Blg, int ldb, long long bO, long long bI,
    const float* __restrict__ bias, const float* __restrict__ bias2,
    const float* __restrict__ res,
    float* __restrict__ Cf, u16* __restrict__ Chi, u16* __restrict__ Clo,
    int ldc, long long cO, long long cI, int K, float alpha)
{
    constexpr int AP = 40;
    constexpr int ASZ = 128 * AP;
    constexpr int BROWS = TRANSB ? BN : 32;
    constexpr int BP = TRANSB ? 40 : (BN + 8);
    constexpr int BSZ = BROWS * BP;
    constexpr int STG = 2 * ASZ + 2 * BSZ;
    extern __shared__ u16 sm[];

    const int t = threadIdx.x;
    const int w = t >> 5, lane = t & 31;
    const int g = lane >> 2, th = lane & 3;
    const int m0 = blockIdx.y * 128, n0 = blockIdx.x * BN;
    const int z = blockIdx.z;
    const long long offA = (long long)(z >> 4) * aO + (long long)(z & 15) * aI;
    const long long offB = (long long)(z >> 4) * bO + (long long)(z & 15) * bI;
    const long long offC = (long long)(z >> 4) * cO + (long long)(z & 15) * cI;
    const u16* Ah_g = Ahg + offA;
    const u16* Al_g = Alg + offA;
    const u16* Bh_g = Bhg + offB;
    const u16* Bl_g = Blg + offB;
    const float* bsel = ((z & 15) && bias2) ? bias2 : bias;

    constexpr int MFRAG = (BN == 128) ? 4 : 2;
    const int wm = (BN == 128) ? ((w >> 2) * 64) : ((w >> 1) * 32);
    const int wn = (BN == 128) ? ((w & 3) * 32) : ((w & 1) * 32);

    const int lrow = (lane & 7) + ((lane & 8) ? 8 : 0);
    const int lcol = (lane & 16) ? 8 : 0;
    const uint32_t smbase = smem_u32(sm);

    float acc[MFRAG][4][4] = {};

    auto issue = [&](int kt, int s) {
        const uint32_t ah = smbase + (uint32_t)(s * STG) * 2;
        const uint32_t al = ah + ASZ * 2;
        const uint32_t bh = al + ASZ * 2;
        const uint32_t bl = bh + BSZ * 2;
        #pragma unroll
        for (int c = t; c < 512; c += 256) {
            int row = c >> 2, k8 = (c & 3) * 8;
            size_t gidx = (size_t)(m0 + row) * lda + kt + k8;
            uint32_t doff = (uint32_t)(row * AP + k8) * 2;
            cpa16(ah + doff, Ah_g + gidx);
            cpa16(al + doff, Al_g + gidx);
        }
        if (TRANSB) {
            #pragma unroll
            for (int c = t; c < BN * 4; c += 256) {
                int row = c >> 2, k8 = (c & 3) * 8;
                size_t gidx = (size_t)(n0 + row) * ldb + kt + k8;
                uint32_t doff = (uint32_t)(row * BP + k8) * 2;
                cpa16(bh + doff, Bh_g + gidx);
                cpa16(bl + doff, Bl_g + gidx);
            }
        } else {
            constexpr int CPR = BN / 8;
            #pragma unroll
            for (int c = t; c < 32 * CPR; c += 256) {
                int row = c / CPR, n8 = (c % CPR) * 8;
                size_t gidx = (size_t)(kt + row) * ldb + n0 + n8;
                uint32_t doff = (uint32_t)(row * BP + n8) * 2;
                cpa16(bh + doff, Bh_g + gidx);
                cpa16(bl + doff, Bl_g + gidx);
            }
        }
        cpacommit();
    };

    const int tiles = K >> 5;
    #pragma unroll
    for (int p = 0; p < NSTG - 1 && p < tiles; p++) issue(p << 5, p % NSTG);

    for (int i = 0; i < tiles; i++) {
        cpawait<NSTG - 2>();
        __syncthreads();
        {
            int nx = i + NSTG - 1;
            if (nx < tiles) issue(nx << 5, nx % NSTG);
        }
        const int s = i % NSTG;
        const u16* Ah_s = sm + s * STG;
        const u16* Al_s = Ah_s + ASZ;
        const u16* Bh_s = Al_s + ASZ;
        const u16* Bl_s = Bh_s + BSZ;
        const uint32_t bh_base = smbase + (uint32_t)(s * STG + 2 * ASZ) * 2;
        const uint32_t bl_base = bh_base + BSZ * 2;

        #pragma unroll
        for (int ks = 0; ks < 2; ks++) {
            int ko = ks * 16;
            uint32_t bhf[4][2], blf[4][2];
            if (TRANSB) {
                #pragma unroll
                for (int ni = 0; ni < 4; ni++) {
                    int n = wn + ni * 8 + g;
                    bhf[ni][0] = *(const uint32_t*)&Bh_s[n * BP + ko + 2 * th];
                    bhf[ni][1] = *(const uint32_t*)&Bh_s[n * BP + ko + 8 + 2 * th];
                    blf[ni][0] = *(const uint32_t*)&Bl_s[n * BP + ko + 2 * th];
                    blf[ni][1] = *(const uint32_t*)&Bl_s[n * BP + ko + 8 + 2 * th];
                }
            } else {
                #pragma unroll
                for (int pr = 0; pr < 2; pr++) {
                    uint32_t off = (uint32_t)(((ko + lrow) * BP + wn + pr * 16 + lcol) * 2);
                    uint32_t r[4];
                    ldsm4t(r, bh_base + off);
                    bhf[pr*2][0]=r[0]; bhf[pr*2][1]=r[1]; bhf[pr*2+1][0]=r[2]; bhf[pr*2+1][1]=r[3];
                    ldsm4t(r, bl_base + off);
                    blf[pr*2][0]=r[0]; blf[pr*2][1]=r[1]; blf[pr*2+1][0]=r[2]; blf[pr*2+1][1]=r[3];
                }
            }
            uint32_t af[MFRAG][4];
            #pragma unroll
            for (int mi = 0; mi < MFRAG; mi++) {
                int mr = wm + mi * 16 + g;
                af[mi][0] = *(const uint32_t*)&Ah_s[(mr    ) * AP + ko + 2 * th];
                af[mi][1] = *(const uint32_t*)&Ah_s[(mr + 8) * AP + ko + 2 * th];
                af[mi][2] = *(const uint32_t*)&Ah_s[(mr    ) * AP + ko + 8 + 2 * th];
                af[mi][3] = *(const uint32_t*)&Ah_s[(mr + 8) * AP + ko + 8 + 2 * th];
            }
            #pragma unroll
            for (int mi = 0; mi < MFRAG; mi++)
                #pragma unroll
                for (int ni = 0; ni < 4; ni++) {
                    mma16(acc[mi][ni], af[mi], bhf[ni]);
                    mma16(acc[mi][ni], af[mi], blf[ni]);
                }
            #pragma unroll
            for (int mi = 0; mi < MFRAG; mi++) {
                int mr = wm + mi * 16 + g;
                af[mi][0] = *(const uint32_t*)&Al_s[(mr    ) * AP + ko + 2 * th];
                af[mi][1] = *(const uint32_t*)&Al_s[(mr + 8) * AP + ko + 2 * th];
                af[mi][2] = *(const uint32_t*)&Al_s[(mr    ) * AP + ko + 8 + 2 * th];
                af[mi][3] = *(const uint32_t*)&Al_s[(mr + 8) * AP + ko + 8 + 2 * th];
            }
            #pragma unroll
            for (int mi = 0; mi < MFRAG; mi++)
                #pragma unroll
                for (int ni = 0; ni < 4; ni++)
                    mma16(acc[mi][ni], af[mi], bhf[ni]);
        }
    }

    // ---- epilogue ----
    #pragma unroll
    for (int mi = 0; mi < MFRAG; mi++) {
        #pragma unroll
        for (int ni = 0; ni < 4; ni++) {
            int col = n0 + wn + ni * 8 + th * 2;
            #pragma unroll
            for (int half = 0; half < 2; half++) {
                int row = m0 + wm + mi * 16 + g + half * 8;
                float v0 = acc[mi][ni][half * 2 + 0] * alpha;
                float v1 = acc[mi][ni][half * 2 + 1] * alpha;
                if (bsel) { v0 += bsel[col]; v1 += bsel[col + 1]; }
                if (RES) {
                    v0 += res[(size_t)row * ldc + col];
                    v1 += res[(size_t)row * ldc + col + 1];
                }
                if (GELU) {
                    v0 = 0.5f * v0 * (1.0f + erff(v0 * 0.70710678118654752f));
                    v1 = 0.5f * v1 * (1.0f + erff(v1 * 0.70710678118654752f));
                }
                size_t idx = offC + (size_t)row * ldc + col;
                if (OUTM == OUT_SPLIT) {
                    u16 h0, l0, h1, l1;
                    splitw(v0, h0, l0); splitw(v1, h1, l1);
                    *(uint32_t*)&Chi[idx] = (uint32_t)h0 | ((uint32_t)h1 << 16);
                    *(uint32_t*)&Clo[idx] = (uint32_t)l0 | ((uint32_t)l1 << 16);
                } else {
                    *(float2*)&Cf[idx] = make_float2(v0, v1);
                }
            }
        }
    }
}

// ---------------- host orchestration ----------------
extern "C" void kernel_launch(void* const* d_in, const int* in_sizes, int n_in,
                              void* d_out, int out_size) {
    (void)in_sizes; (void)n_in; (void)out_size;
    const float* x     = (const float*)d_in[0];
    const float* sigma = (const float*)d_in[1];
    const float* U     = (const float*)d_in[2];
    const float* V     = (const float*)d_in[3];
    const float* Wqkv1 = (const float*)d_in[4];
    const float* Wqkv2 = (const float*)d_in[5];
    const float* Wp1   = (const float*)d_in[6];
    const float* bp1   = (const float*)d_in[7];
    const float* Wp2   = (const float*)d_in[8];
    const float* bp2   = (const float*)d_in[9];
    const float* Wo    = (const float*)d_in[10];
    const float* bo    = (const float*)d_in[11];
    const float* gO    = (const float*)d_in[12];
    const float* bO    = (const float*)d_in[13];
    const float* g1    = (const float*)d_in[14];
    const float* b1    = (const float*)d_in[15];
    const float* g2    = (const float*)d_in[16];
    const float* b2    = (const float*)d_in[17];
    const float* Wm1   = (const float*)d_in[18];
    const float* bm1   = (const float*)d_in[19];
    const float* Wm2   = (const float*)d_in[20];
    const float* bm2   = (const float*)d_in[21];
    const float* gf    = (const float*)d_in[22];
    const float* bf    = (const float*)d_in[23];

    float *px, *ptmp, *pad;
    u16 *wh, *wl, *hh, *hl, *x12h, *x12l, *q12h, *q12l;
    u16 *vah, *val, *ph_, *pl_, *mh, *ml;
    cudaGetSymbolAddress((void**)&px,   g_x);
    cudaGetSymbolAddress((void**)&ptmp, g_tmp);
    cudaGetSymbolAddress((void**)&pad,  g_adapt);
    cudaGetSymbolAddress((void**)&wh,   g_wh);
    cudaGetSymbolAddress((void**)&wl,   g_wl);
    cudaGetSymbolAddress((void**)&hh,   g_hh);
    cudaGetSymbolAddress((void**)&hl,   g_hl);
    cudaGetSymbolAddress((void**)&x12h, g_x12h);
    cudaGetSymbolAddress((void**)&x12l, g_x12l);
    cudaGetSymbolAddress((void**)&q12h, g_q12h);
    cudaGetSymbolAddress((void**)&q12l, g_q12l);
    cudaGetSymbolAddress((void**)&vah,  g_vah);
    cudaGetSymbolAddress((void**)&val,  g_val);
    cudaGetSymbolAddress((void**)&ph_,  g_ph);
    cudaGetSymbolAddress((void**)&pl_,  g_pl);
    cudaGetSymbolAddress((void**)&mh,   g_mh);
    cudaGetSymbolAddress((void**)&ml,   g_ml);

    const long long QS = (long long)NTOK * 3 * ND;   // q12 branch stride
    const long long XS = (long long)NTOK * ND;       // x12 branch stride
    u16 *q1h = q12h, *q1l = q12l, *q2h = q12h + QS, *q2l = q12l + QS;

    // dynamic smem sizes (bytes)
    const int SM_B128_S2 = 2 * (2*128*40 + 2*32*136) * 2;   // 75776
    const int SM_B64_S3  = 3 * (2*128*40 + 2*32*72)  * 2;   // 89088
    const int SM_FLASH   = (4*128*72 + 2*6*64*72) * 2;      // 184320
    cudaFuncSetAttribute((const void*)mma_gemm<64, false,false,false,OUT_SPLIT,3>, cudaFuncAttributeMaxDynamicSharedMemorySize, SM_B64_S3);
    cudaFuncSetAttribute((const void*)mma_gemm<64, false,false,false,OUT_F32,  3>, cudaFuncAttributeMaxDynamicSharedMemorySize, SM_B64_S3);
    cudaFuncSetAttribute((const void*)mma_gemm<64, false,false,true, OUT_F32,  3>, cudaFuncAttributeMaxDynamicSharedMemorySize, SM_B64_S3);
    cudaFuncSetAttribute((const void*)mma_gemm<128,false,false,false,OUT_SPLIT,2>, cudaFuncAttributeMaxDynamicSharedMemorySize, SM_B128_S2);
    cudaFuncSetAttribute((const void*)mma_gemm<128,false,true, false,OUT_SPLIT,2>, cudaFuncAttributeMaxDynamicSharedMemorySize, SM_B128_S2);
    cudaFuncSetAttribute((const void*)flash_kernel, cudaFuncAttributeMaxDynamicSharedMemorySize, SM_FLASH);

    copy_kernel<<<NTOK * ND / 256, 256>>>(x, px, NTOK * ND);

    // pre-split weights, grouped by type (7 launches)
    wsplit_kernel<<<2048, 256>>>(Wp1,   wh + OFF_P1, wl + OFF_P1, (size_t)NL*512*ND);
    wsplit_kernel<<<2048, 256>>>(Wp2,   wh + OFF_P2, wl + OFF_P2, (size_t)NL*512*ND);
    wsplit_kernel<<<4096, 256>>>(Wqkv1, wh + OFF_Q1, wl + OFF_Q1, (size_t)NL*ND*3*ND);
    wsplit_kernel<<<4096, 256>>>(Wqkv2, wh + OFF_Q2, wl + OFF_Q2, (size_t)NL*ND*3*ND);
    wsplit_kernel<<<2048, 256>>>(Wo,    wh + OFF_O,  wl + OFF_O,  (size_t)NL*ND*ND);
    wsplit_kernel<<<4096, 256>>>(Wm1,   wh + OFF_M1, wl + OFF_M1, (size_t)NL*ND*4*ND);
    wsplit_kernel<<<4096, 256>>>(Wm2,   wh + OFF_M2, wl + OFF_M2, (size_t)NL*4*ND*ND);

    for (int l = 0; l < NL; l++) {
        const size_t oP1 = OFF_P1 + (size_t)l*512*ND;
        const size_t oQ1 = OFF_Q1 + (size_t)l*ND*3*ND;
        const size_t oO  = OFF_O  + (size_t)l*ND*ND;
        const size_t oM1 = OFF_M1 + (size_t)l*ND*4*ND;
        const size_t oM2 = OFF_M2 + (size_t)l*4*ND*ND;

        adapt_kernel<<<1, 256>>>(U + (size_t)l * ND * 4, V + (size_t)l * 4 * ND, sigma + l, pad);
        ln_kernel<true, false, true><<<NTOK, 256>>>(px, g1 + l*ND, b1 + l*ND, pad, nullptr, nullptr, hh, hl);

        // x1p & x2p batched (BN=64, 3-stage): z=0 -> a[:, :512]@Wp1+bp1; z=1 -> a[:, 512:]@Wp2+bp2
        mma_gemm<64,false,false,false,OUT_SPLIT,3><<<dim3(16,16,2), 256, SM_B64_S3>>>(
            hh, hl, ND, 0, 512,
            wh+oP1, wl+oP1, ND, 0, (long long)(OFF_P2 - OFF_P1),
            bp1 + l*ND, bp2 + l*ND, nullptr,
            nullptr, x12h, x12l, ND, 0, XS, 512, 1.0f);

        // qkv batched into ONE launch (BN=128, 2-stage): z=0 -> x1p@Wqkv1; z=1 -> x2p@Wqkv2
        mma_gemm<128,false,false,false,OUT_SPLIT,2><<<dim3(24,16,2), 256, SM_B128_S2>>>(
            x12h, x12l, ND, 0, XS,
            wh+oQ1, wl+oQ1, 3*ND, 0, (long long)(OFF_Q2 - OFF_Q1),
            nullptr, nullptr, nullptr,
            nullptr, q12h, q12l, 3*ND, 0, QS, ND, 1.0f);

        // fused attention
        vavg_t_kernel<<<dim3(16, 32), 256>>>(q1h, q1l, q2h, q2l, vah, val);
        flash_kernel<<<dim3(8, 32), 256, SM_FLASH>>>(q1h, q1l, q2h, q2l, vah, val, ph_, pl_);

        // out proj (BN=64, fp32) + post-LN + residual
        mma_gemm<64,false,false,false,OUT_F32,3><<<dim3(16,16), 256, SM_B64_S3>>>(
            ph_, pl_, ND, 0, 0, wh+oO, wl+oO, ND, 0, 0,
            bo + l*ND, nullptr, nullptr, ptmp, nullptr, nullptr, ND, 0, 0, ND, 1.0f);
        ln_kernel<false, true, false><<<NTOK, 256>>>(ptmp, gO + l*ND, bO + l*ND, nullptr, px, px, nullptr, nullptr);

        // MLP (Wm1 BN=128 — R9-proven config)
        ln_kernel<false, false, true><<<NTOK, 256>>>(px, g2 + l*ND, b2 + l*ND, nullptr, nullptr, nullptr, hh, hl);
        mma_gemm<128,false,true,false,OUT_SPLIT,2><<<dim3(32,16), 256, SM_B128_S2>>>(
            hh, hl, ND, 0, 0, wh+oM1, wl+oM1, 4*ND, 0, 0,
            bm1 + (size_t)l*4*ND, nullptr, nullptr, nullptr, mh, ml, 4*ND, 0, 0, ND, 1.0f);
        mma_gemm<64,false,false,true,OUT_F32,3><<<dim3(16,16), 256, SM_B64_S3>>>(
            mh, ml, 4*ND, 0, 0, wh+oM2, wl+oM2, ND, 0, 0,
            bm2 + l*ND, nullptr, px, px, nullptr, nullptr, ND, 0, 0, 4*ND, 1.0f);
    }

    ln_kernel<false, false, false><<<NTOK, 256>>>(px, gf, bf, nullptr, nullptr, (float*)d_out, nullptr, nullptr);
}

// round 13
// speedup vs baseline: 1.0779x; 1.0514x over previous
#include <cuda_runtime.h>
#include <cuda_fp16.h>
#include <math.h>
#include <stdint.h>

#define NL 4
#define NB 2
#define NS 1024
#define ND 1024
#define NH 16
#define NDH 64
#define NTOK (NB*NS)        // 2048
#define ATT_SCALE 0.125f
#define LN_EPS 1e-5f

typedef unsigned short u16;

// ---------------- scratch (static device globals: alloc-free) ----------------
__device__ float g_x    [NTOK*ND];
__device__ float g_tmp  [NTOK*ND];
__device__ float g_adapt[ND];

// split fp16 weights, grouped by TYPE (contiguous across layers)
#define WTOT 67108864ULL
#define OFF_P1 0ULL
#define OFF_P2 2097152ULL
#define OFF_Q1 4194304ULL
#define OFF_Q2 16777216ULL
#define OFF_O  29360128ULL
#define OFF_M1 33554432ULL
#define OFF_M2 50331648ULL
__device__ u16 g_wh [WTOT];
__device__ u16 g_wl [WTOT];
__device__ u16 g_hh [NTOK*ND],       g_hl [NTOK*ND];          // LN out
__device__ u16 g_x12h[2*NTOK*ND],    g_x12l[2*NTOK*ND];       // x1p|x2p (batched)
__device__ u16 g_q12h[2*NTOK*3*ND],  g_q12l[2*NTOK*3*ND];     // qkv1|qkv2 (batched)
__device__ u16 g_vah[32*NS*NDH],     g_val[32*NS*NDH];        // vavg TRANSPOSED [z][d][k]
__device__ u16 g_ph [NTOK*ND],       g_pl [NTOK*ND];          // attn out
__device__ u16 g_mh [NTOK*4*ND],     g_ml [NTOK*4*ND];        // gelu out

// ---------------- helpers ----------------
__device__ __forceinline__ uint32_t smem_u32(const void* p) {
    uint32_t a;
    asm("{ .reg .u64 t; cvta.to.shared.u64 t, %1; cvt.u32.u64 %0, t; }" : "=r"(a) : "l"(p));
    return a;
}
__device__ __forceinline__ void splitw(float v, u16& h, u16& l) {
    __half hh = __float2half_rn(v);
    h = __half_as_ushort(hh);
    l = __half_as_ushort(__float2half_rn(v - __half2float(hh)));
}
__device__ __forceinline__ void split2(float x, float y, uint32_t& hi, uint32_t& lo) {
    u16 hx, lx, hy, ly;
    splitw(x, hx, lx); splitw(y, hy, ly);
    hi = (uint32_t)hx | ((uint32_t)hy << 16);
    lo = (uint32_t)lx | ((uint32_t)ly << 16);
}
__device__ __forceinline__ float joinw(u16 h, u16 l) {
    return __half2float(__ushort_as_half(h)) + __half2float(__ushort_as_half(l));
}
__device__ __forceinline__ void mma16(float* c, const uint32_t* a, const uint32_t* b) {
    asm volatile(
        "mma.sync.aligned.m16n8k16.row.col.f32.f16.f16.f32 "
        "{%0,%1,%2,%3},{%4,%5,%6,%7},{%8,%9},{%0,%1,%2,%3};\n"
        : "+f"(c[0]), "+f"(c[1]), "+f"(c[2]), "+f"(c[3])
        : "r"(a[0]), "r"(a[1]), "r"(a[2]), "r"(a[3]), "r"(b[0]), "r"(b[1]));
}
__device__ __forceinline__ void ldsm4t(uint32_t* r, uint32_t addr) {
    asm volatile("ldmatrix.sync.aligned.m8n8.x4.trans.shared.b16 {%0,%1,%2,%3}, [%4];"
        : "=r"(r[0]), "=r"(r[1]), "=r"(r[2]), "=r"(r[3]) : "r"(addr));
}
__device__ __forceinline__ void ldsm4(uint32_t* r, uint32_t addr) {
    asm volatile("ldmatrix.sync.aligned.m8n8.x4.shared.b16 {%0,%1,%2,%3}, [%4];"
        : "=r"(r[0]), "=r"(r[1]), "=r"(r[2]), "=r"(r[3]) : "r"(addr));
}
__device__ __forceinline__ void cpa16(uint32_t dst, const void* src) {
    asm volatile("cp.async.cg.shared.global [%0], [%1], 16;" :: "r"(dst), "l"(src));
}
__device__ __forceinline__ void cpacommit() { asm volatile("cp.async.commit_group;"); }
template<int N> __device__ __forceinline__ void cpawait() {
    asm volatile("cp.async.wait_group %0;" :: "n"(N));
}

template<bool MAXRED>
__device__ __forceinline__ float blk_reduce(float v, float* red) {
    int t = threadIdx.x;  // 256 threads
    red[t] = v; __syncthreads();
    #pragma unroll
    for (int o = 128; o > 0; o >>= 1) {
        if (t < o) red[t] = MAXRED ? fmaxf(red[t], red[t + o]) : (red[t] + red[t + o]);
        __syncthreads();
    }
    float r = red[0];
    __syncthreads();
    return r;
}

// ---------------- tiny kernels ----------------
__global__ void copy_kernel(const float* __restrict__ in, float* __restrict__ out, int n) {
    int i = blockIdx.x * 256 + threadIdx.x;
    if (i < n) out[i] = in[i];
}

__global__ void wsplit_kernel(const float* __restrict__ w, u16* __restrict__ h,
                              u16* __restrict__ l, size_t n) {
    for (size_t i = ((size_t)blockIdx.x * 256 + threadIdx.x) * 4; i < n;
         i += (size_t)gridDim.x * 1024) {
        float4 v = *(const float4*)(w + i);
        u16 h0,l0,h1,l1,h2,l2,h3,l3;
        splitw(v.x,h0,l0); splitw(v.y,h1,l1); splitw(v.z,h2,l2); splitw(v.w,h3,l3);
        *(uint2*)(h + i) = make_uint2((uint32_t)h0 | ((uint32_t)h1<<16),
                                      (uint32_t)h2 | ((uint32_t)h3<<16));
        *(uint2*)(l + i) = make_uint2((uint32_t)l0 | ((uint32_t)l1<<16),
                                      (uint32_t)l2 | ((uint32_t)l3<<16));
    }
}

__global__ void adapt_kernel(const float* __restrict__ U, const float* __restrict__ V,
                             const float* __restrict__ sigma, float* __restrict__ adapt) {
    __shared__ float red[256];
    __shared__ float vsum[4];
    int t = threadIdx.x;
    for (int r = 0; r < 4; r++) {
        float s = 0.f;
        for (int j = t; j < ND; j += 256) s += V[r * ND + j];
        s = blk_reduce<false>(s, red);
        if (t == 0) vsum[r] = s;
        __syncthreads();
    }
    float sg = sigma[0];
    for (int i = t; i < ND; i += 256) {
        float a = 0.f;
        #pragma unroll
        for (int r = 0; r < 4; r++) a += U[i * 4 + r] * vsum[r];
        adapt[i] = a * sg;
    }
}

template<bool ADD_ADAPT, bool RES, bool SPLIT>
__global__ void ln_kernel(const float* __restrict__ in, const float* __restrict__ g,
                          const float* __restrict__ b, const float* __restrict__ adapt,
                          const float* __restrict__ res, float* __restrict__ out,
                          u16* __restrict__ oh, u16* __restrict__ ol) {
    __shared__ float red[256];
    int row = blockIdx.x, t = threadIdx.x;
    const float* rin = in + (size_t)row * ND;
    float v[4];
    #pragma unroll
    for (int i = 0; i < 4; i++) v[i] = rin[t + i * 256];
    float s = v[0] + v[1] + v[2] + v[3];
    float mean = blk_reduce<false>(s, red) * (1.0f / ND);
    float sq = 0.f;
    #pragma unroll
    for (int i = 0; i < 4; i++) { float d = v[i] - mean; sq += d * d; }
    float var = blk_reduce<false>(sq, red) * (1.0f / ND);
    float inv = rsqrtf(var + LN_EPS);
    #pragma unroll
    for (int i = 0; i < 4; i++) {
        int c = t + i * 256;
        float o = (v[i] - mean) * inv * g[c] + b[c];
        if (ADD_ADAPT) o += adapt[c];
        if (RES)       o += res[(size_t)row * ND + c];
        size_t idx = (size_t)row * ND + c;
        if (SPLIT) { u16 hh, ll; splitw(o, hh, ll); oh[idx] = hh; ol[idx] = ll; }
        else out[idx] = o;
    }
}

// vavg transposed: out[z][d][k] = 0.5*(v1+v2)
__global__ void vavg_t_kernel(const u16* __restrict__ q1h, const u16* __restrict__ q1l,
                              const u16* __restrict__ q2h, const u16* __restrict__ q2l,
                              u16* __restrict__ oh, u16* __restrict__ ol) {
    __shared__ float tile[64][65];
    int z = blockIdx.y, b = z >> 4, h = z & 15;
    int kt = blockIdx.x * 64;
    int t = threadIdx.x;
    for (int idx = t; idx < 4096; idx += 256) {
        int k = idx >> 6, d = idx & 63;
        size_t src = (size_t)(b * NS + kt + k) * 3072 + 2048 + h * 64 + d;
        tile[k][d] = 0.5f * (joinw(q1h[src], q1l[src]) + joinw(q2h[src], q2l[src]));
    }
    __syncthreads();
    for (int idx = t; idx < 4096; idx += 256) {
        int d = idx >> 6, k = idx & 63;
        float v = tile[k][d];
        u16 hh, ll; splitw(v, hh, ll);
        size_t dst = ((size_t)z * 64 + d) * 1024 + kt + k;
        oh[dst] = hh; ol[dst] = ll;
    }
}

// ---------------- fused dual-softmax-diff flash attention ----------------
__global__ void __launch_bounds__(256, 1) flash_kernel(
    const u16* __restrict__ q1h, const u16* __restrict__ q1l,
    const u16* __restrict__ q2h, const u16* __restrict__ q2l,
    const u16* __restrict__ vth, const u16* __restrict__ vtl,
    u16* __restrict__ oh, u16* __restrict__ ol)
{
    constexpr int QP = 72, KP = 72;
    constexpr int QSZ = 128 * QP;
    constexpr int KSZ = 64 * KP;
    constexpr int STGH = 6 * KSZ;
    extern __shared__ u16 sm[];
    const uint32_t smbase = smem_u32(sm);

    const int t = threadIdx.x, w = t >> 5, lane = t & 31;
    const int g = lane >> 2, th = lane & 3;
    const int z = blockIdx.y, b = z >> 4, h = z & 15;
    const int q0 = blockIdx.x * 128;
    const int wm = w * 16;
    const int arow = lane & 15;            // ldsm non-trans lane roles (A/Q frags)
    const int acol = (lane >> 4) << 3;

    for (int c = t; c < 128 * 8; c += 256) {
        int row = c >> 3, c8 = (c & 7) * 8;
        size_t gidx = (size_t)(b * NS + q0 + row) * 3072 + h * 64 + c8;
        uint32_t doff = (uint32_t)(row * QP + c8) * 2;
        cpa16(smbase + (0*QSZ)*2 + doff, q1h + gidx);
        cpa16(smbase + (1*QSZ)*2 + doff, q1l + gidx);
        cpa16(smbase + (2*QSZ)*2 + doff, q2h + gidx);
        cpa16(smbase + (3*QSZ)*2 + doff, q2l + gidx);
    }
    cpacommit();

    auto issue_kv = [&](int kt, int s) {
        const uint32_t sb = smbase + (uint32_t)(4*QSZ + s*STGH) * 2;
        for (int c = t; c < 64 * 8; c += 256) {
            int row = c >> 3, c8 = (c & 7) * 8;
            size_t kidx = (size_t)(b * NS + kt + row) * 3072 + 1024 + h * 64 + c8;
            uint32_t doff = (uint32_t)(row * KP + c8) * 2;
            cpa16(sb + (0*KSZ)*2 + doff, q1h + kidx);
            cpa16(sb + (1*KSZ)*2 + doff, q1l + kidx);
            cpa16(sb + (2*KSZ)*2 + doff, q2h + kidx);
            cpa16(sb + (3*KSZ)*2 + doff, q2l + kidx);
            size_t vidx = ((size_t)z * 64 + row) * 1024 + kt + c8;
            cpa16(sb + (4*KSZ)*2 + doff, vth + vidx);
            cpa16(sb + (5*KSZ)*2 + doff, vtl + vidx);
        }
        cpacommit();
    };
    issue_kv(0, 0);

    float O1[8][4] = {}, O2[8][4] = {};
    float m1[2] = {-1e30f, -1e30f}, l1[2] = {0.f, 0.f};
    float m2[2] = {-1e30f, -1e30f}, l2[2] = {0.f, 0.f};

    for (int kt_i = 0; kt_i < 16; kt_i++) {
        cpawait<0>();
        __syncthreads();
        if (kt_i + 1 < 16) issue_kv((kt_i + 1) * 64, (kt_i + 1) & 1);

        const int s = kt_i & 1;
        const u16* stg = sm + 4*QSZ + s*STGH;
        const u16* Vh_s = stg + 4*KSZ;
        const u16* Vl_s = stg + 5*KSZ;

        #pragma unroll
        for (int br = 0; br < 2; br++) {
            const uint32_t qh_base = smbase + (uint32_t)((br*2 + 0)*QSZ) * 2;
            const uint32_t ql_base = qh_base + (uint32_t)QSZ * 2;
            const u16* Kh_s = stg + (br*2 + 0)*KSZ;
            const u16* Kl_s = stg + (br*2 + 1)*KSZ;
            float (*O)[4] = br ? O2 : O1;
            float* m = br ? m2 : m1;
            float* l = br ? l2 : l1;

            float c[8][4] = {};
            #pragma unroll
            for (int ks = 0; ks < 4; ks++) {
                int ko = ks * 16;
                uint32_t bh[8][2], bl[8][2];
                #pragma unroll
                for (int ni = 0; ni < 8; ni++) {
                    int n = ni * 8 + g;
                    bh[ni][0] = *(const uint32_t*)&Kh_s[n * KP + ko + 2*th];
                    bh[ni][1] = *(const uint32_t*)&Kh_s[n * KP + ko + 8 + 2*th];
                    bl[ni][0] = *(const uint32_t*)&Kl_s[n * KP + ko + 2*th];
                    bl[ni][1] = *(const uint32_t*)&Kl_s[n * KP + ko + 8 + 2*th];
                }
                uint32_t af[4];
                ldsm4(af, qh_base + (uint32_t)(((wm + arow) * QP + ko + acol) * 2));
                #pragma unroll
                for (int ni = 0; ni < 8; ni++) {
                    mma16(c[ni], af, bh[ni]);
                    mma16(c[ni], af, bl[ni]);
                }
                ldsm4(af, ql_base + (uint32_t)(((wm + arow) * QP + ko + acol) * 2));
                #pragma unroll
                for (int ni = 0; ni < 8; ni++)
                    mma16(c[ni], af, bh[ni]);
            }
            #pragma unroll
            for (int ni = 0; ni < 8; ni++) {
                c[ni][0] *= ATT_SCALE; c[ni][1] *= ATT_SCALE;
                c[ni][2] *= ATT_SCALE; c[ni][3] *= ATT_SCALE;
            }

            float mx0 = -1e30f, mx1 = -1e30f;
            #pragma unroll
            for (int ni = 0; ni < 8; ni++) {
                mx0 = fmaxf(mx0, fmaxf(c[ni][0], c[ni][1]));
                mx1 = fmaxf(mx1, fmaxf(c[ni][2], c[ni][3]));
            }
            mx0 = fmaxf(mx0, __shfl_xor_sync(0xffffffffu, mx0, 1));
            mx0 = fmaxf(mx0, __shfl_xor_sync(0xffffffffu, mx0, 2));
            mx1 = fmaxf(mx1, __shfl_xor_sync(0xffffffffu, mx1, 1));
            mx1 = fmaxf(mx1, __shfl_xor_sync(0xffffffffu, mx1, 2));
            float mn0 = fmaxf(m[0], mx0), mn1 = fmaxf(m[1], mx1);
            float a0 = __expf(m[0] - mn0), a1 = __expf(m[1] - mn1);
            m[0] = mn0; m[1] = mn1;

            uint32_t pfh[4][4], pfl[4][4];
            float s0 = 0.f, s1 = 0.f;
            #pragma unroll
            for (int ni = 0; ni < 8; ni++) {
                float p0 = __expf(c[ni][0] - mn0);
                float p1 = __expf(c[ni][1] - mn0);
                float p2 = __expf(c[ni][2] - mn1);
                float p3 = __expf(c[ni][3] - mn1);
                s0 += p0 + p1; s1 += p2 + p3;
                uint32_t h01, l01, h23, l23;
                split2(p0, p1, h01, l01);
                split2(p2, p3, h23, l23);
                int j = ni >> 1, sl = (ni & 1) * 2;
                pfh[j][sl]   = h01; pfl[j][sl]   = l01;
                pfh[j][sl+1] = h23; pfl[j][sl+1] = l23;
            }
            s0 += __shfl_xor_sync(0xffffffffu, s0, 1);
            s0 += __shfl_xor_sync(0xffffffffu, s0, 2);
            s1 += __shfl_xor_sync(0xffffffffu, s1, 1);
            s1 += __shfl_xor_sync(0xffffffffu, s1, 2);
            l[0] = l[0] * a0 + s0;
            l[1] = l[1] * a1 + s1;

            #pragma unroll
            for (int ni = 0; ni < 8; ni++) {
                O[ni][0] *= a0; O[ni][1] *= a0;
                O[ni][2] *= a1; O[ni][3] *= a1;
            }

            #pragma unroll
            for (int j = 0; j < 4; j++) {
                int ko = j * 16;
                #pragma unroll
                for (int nd = 0; nd < 8; nd++) {
                    int n = nd * 8 + g;
                    uint32_t vb[2], vbl[2];
                    vb[0]  = *(const uint32_t*)&Vh_s[n * KP + ko + 2*th];
                    vb[1]  = *(const uint32_t*)&Vh_s[n * KP + ko + 8 + 2*th];
                    vbl[0] = *(const uint32_t*)&Vl_s[n * KP + ko + 2*th];
                    vbl[1] = *(const uint32_t*)&Vl_s[n * KP + ko + 8 + 2*th];
                    mma16(O[nd], pfh[j], vb);
                    mma16(O[nd], pfh[j], vbl);
                    mma16(O[nd], pfl[j], vb);
                }
            }
        }
    }

    float i10 = 1.f / l1[0], i11 = 1.f / l1[1];
    float i20 = 1.f / l2[0], i21 = 1.f / l2[1];
    #pragma unroll
    for (int ni = 0; ni < 8; ni++) {
        int col = h * 64 + ni * 8 + th * 2;
        size_t r0 = (size_t)(b * NS + q0 + wm + g    ) * ND + col;
        size_t r1 = (size_t)(b * NS + q0 + wm + g + 8) * ND + col;
        float v0 = O1[ni][0] * i10 - O2[ni][0] * i20;
        float v1 = O1[ni][1] * i10 - O2[ni][1] * i20;
        float v2 = O1[ni][2] * i11 - O2[ni][2] * i21;
        float v3 = O1[ni][3] * i11 - O2[ni][3] * i21;
        uint32_t H01, L01, H23, L23;
        split2(v0, v1, H01, L01);
        split2(v2, v3, H23, L23);
        *(uint32_t*)&oh[r0] = H01; *(uint32_t*)&ol[r0] = L01;
        *(uint32_t*)&oh[r1] = H23; *(uint32_t*)&ol[r1] = L23;
    }
}

// ---------------- split-fp16 mma.sync GEMM, NSTG-stage pipeline -------------
// A-fragments via non-trans ldmatrix; weights-B via trans ldmatrix.
// bias2: when non-null, blockIdx.z&15 selects bias (batched branch pairs).
#define OUT_F32 0
#define OUT_SPLIT 1

template<int BN, bool GELU, bool RES, int OUTM, int NSTG>
__global__ void __launch_bounds__(256, 2) mma_gemm(
    const u16* __restrict__ Ahg, const u16* __restrict__ Alg, int lda, long long aO, long long aI,
    const u16* __restrict__ Bhg, const u16* __restrict__ Blg, int ldb, long long bO, long long bI,
    const float* __restrict__ bias, const float* __restrict__ bias2,
    const float* __restrict__ res,
    float* __restrict__ Cf, u16* __restrict__ Chi, u16* __restrict__ Clo,
    int ldc, long long cO, long long cI, int K, float alpha)
{
    constexpr int AP = 40;
    constexpr int ASZ = 128 * AP;
    constexpr int BP = BN + 8;
    constexpr int BSZ = 32 * BP;
    constexpr int STG = 2 * ASZ + 2 * BSZ;
    extern __shared__ u16 sm[];

    const int t = threadIdx.x;
    const int w = t >> 5, lane = t & 31;
    const int g = lane >> 2, th = lane & 3;
    const int m0 = blockIdx.y * 128, n0 = blockIdx.x * BN;
    const int z = blockIdx.z;
    const long long offA = (long long)(z >> 4) * aO + (long long)(z & 15) * aI;
    const long long offB = (long long)(z >> 4) * bO + (long long)(z & 15) * bI;
    const long long offC = (long long)(z >> 4) * cO + (long long)(z & 15) * cI;
    const u16* Ah_g = Ahg + offA;
    const u16* Al_g = Alg + offA;
    const u16* Bh_g = Bhg + offB;
    const u16* Bl_g = Blg + offB;
    const float* bsel = ((z & 15) && bias2) ? bias2 : bias;

    constexpr int MFRAG = (BN == 128) ? 4 : 2;
    const int wm = (BN == 128) ? ((w >> 2) * 64) : ((w >> 1) * 32);
    const int wn = (BN == 128) ? ((w & 3) * 32) : ((w & 1) * 32);

    const int lrow = (lane & 7) + ((lane & 8) ? 8 : 0);   // trans-B lane roles
    const int lcol = (lane & 16) ? 8 : 0;
    const int arow = lane & 15;                            // A non-trans lane roles
    const int acol = (lane >> 4) << 3;
    const uint32_t smbase = smem_u32(sm);

    float acc[MFRAG][4][4] = {};

    auto issue = [&](int kt, int s) {
        const uint32_t ah = smbase + (uint32_t)(s * STG) * 2;
        const uint32_t al = ah + ASZ * 2;
        const uint32_t bh = al + ASZ * 2;
        const uint32_t bl = bh + BSZ * 2;
        #pragma unroll
        for (int c = t; c < 512; c += 256) {
            int row = c >> 2, k8 = (c & 3) * 8;
            size_t gidx = (size_t)(m0 + row) * lda + kt + k8;
            uint32_t doff = (uint32_t)(row * AP + k8) * 2;
            cpa16(ah + doff, Ah_g + gidx);
            cpa16(al + doff, Al_g + gidx);
        }
        {
            constexpr int CPR = BN / 8;
            #pragma unroll
            for (int c = t; c < 32 * CPR; c += 256) {
                int row = c / CPR, n8 = (c % CPR) * 8;
                size_t gidx = (size_t)(kt + row) * ldb + n0 + n8;
                uint32_t doff = (uint32_t)(row * BP + n8) * 2;
                cpa16(bh + doff, Bh_g + gidx);
                cpa16(bl + doff, Bl_g + gidx);
            }
        }
        cpacommit();
    };

    const int tiles = K >> 5;
    #pragma unroll
    for (int p = 0; p < NSTG - 1 && p < tiles; p++) issue(p << 5, p % NSTG);

    for (int i = 0; i < tiles; i++) {
        cpawait<NSTG - 2>();
        __syncthreads();
        {
            int nx = i + NSTG - 1;
            if (nx < tiles) issue(nx << 5, nx % NSTG);
        }
        const int s = i % NSTG;
        const uint32_t ah_base = smbase + (uint32_t)(s * STG) * 2;
        const uint32_t al_base = ah_base + ASZ * 2;
        const uint32_t bh_base = al_base + ASZ * 2;
        const uint32_t bl_base = bh_base + BSZ * 2;

        #pragma unroll
        for (int ks = 0; ks < 2; ks++) {
            int ko = ks * 16;
            uint32_t bhf[4][2], blf[4][2];
            #pragma unroll
            for (int pr = 0; pr < 2; pr++) {
                uint32_t off = (uint32_t)(((ko + lrow) * BP + wn + pr * 16 + lcol) * 2);
                uint32_t r[4];
                ldsm4t(r, bh_base + off);
                bhf[pr*2][0]=r[0]; bhf[pr*2][1]=r[1]; bhf[pr*2+1][0]=r[2]; bhf[pr*2+1][1]=r[3];
                ldsm4t(r, bl_base + off);
                blf[pr*2][0]=r[0]; blf[pr*2][1]=r[1]; blf[pr*2+1][0]=r[2]; blf[pr*2+1][1]=r[3];
            }
            uint32_t af[MFRAG][4];
            #pragma unroll
            for (int mi = 0; mi < MFRAG; mi++)
                ldsm4(af[mi], ah_base + (uint32_t)(((wm + mi * 16 + arow) * AP + ko + acol) * 2));
            #pragma unroll
            for (int mi = 0; mi < MFRAG; mi++)
                #pragma unroll
                for (int ni = 0; ni < 4; ni++) {
                    mma16(acc[mi][ni], af[mi], bhf[ni]);
                    mma16(acc[mi][ni], af[mi], blf[ni]);
                }
            #pragma unroll
            for (int mi = 0; mi < MFRAG; mi++)
                ldsm4(af[mi], al_base + (uint32_t)(((wm + mi * 16 + arow) * AP + ko + acol) * 2));
            #pragma unroll
            for (int mi = 0; mi < MFRAG; mi++)
                #pragma unroll
                for (int ni = 0; ni < 4; ni++)
                    mma16(acc[mi][ni], af[mi], bhf[ni]);
        }
    }

    // ---- epilogue ----
    #pragma unroll
    for (int mi = 0; mi < MFRAG; mi++) {
        #pragma unroll
        for (int ni = 0; ni < 4; ni++) {
            int col = n0 + wn + ni * 8 + th * 2;
            #pragma unroll
            for (int half = 0; half < 2; half++) {
                int row = m0 + wm + mi * 16 + g + half * 8;
                float v0 = acc[mi][ni][half * 2 + 0] * alpha;
                float v1 = acc[mi][ni][half * 2 + 1] * alpha;
                if (bsel) { v0 += bsel[col]; v1 += bsel[col + 1]; }
                if (RES) {
                    v0 += res[(size_t)row * ldc + col];
                    v1 += res[(size_t)row * ldc + col + 1];
                }
                if (GELU) {
                    v0 = 0.5f * v0 * (1.0f + erff(v0 * 0.70710678118654752f));
                    v1 = 0.5f * v1 * (1.0f + erff(v1 * 0.70710678118654752f));
                }
                size_t idx = offC + (size_t)row * ldc + col;
                if (OUTM == OUT_SPLIT) {
                    u16 h0, l0, h1, l1;
                    splitw(v0, h0, l0); splitw(v1, h1, l1);
                    *(uint32_t*)&Chi[idx] = (uint32_t)h0 | ((uint32_t)h1 << 16);
                    *(uint32_t*)&Clo[idx] = (uint32_t)l0 | ((uint32_t)l1 << 16);
                } else {
                    *(float2*)&Cf[idx] = make_float2(v0, v1);
                }
            }
        }
    }
}

// ---------------- host orchestration ----------------
extern "C" void kernel_launch(void* const* d_in, const int* in_sizes, int n_in,
                              void* d_out, int out_size) {
    (void)in_sizes; (void)n_in; (void)out_size;
    const float* x     = (const float*)d_in[0];
    const float* sigma = (const float*)d_in[1];
    const float* U     = (const float*)d_in[2];
    const float* V     = (const float*)d_in[3];
    const float* Wqkv1 = (const float*)d_in[4];
    const float* Wqkv2 = (const float*)d_in[5];
    const float* Wp1   = (const float*)d_in[6];
    const float* bp1   = (const float*)d_in[7];
    const float* Wp2   = (const float*)d_in[8];
    const float* bp2   = (const float*)d_in[9];
    const float* Wo    = (const float*)d_in[10];
    const float* bo    = (const float*)d_in[11];
    const float* gO    = (const float*)d_in[12];
    const float* bO    = (const float*)d_in[13];
    const float* g1    = (const float*)d_in[14];
    const float* b1    = (const float*)d_in[15];
    const float* g2    = (const float*)d_in[16];
    const float* b2    = (const float*)d_in[17];
    const float* Wm1   = (const float*)d_in[18];
    const float* bm1   = (const float*)d_in[19];
    const float* Wm2   = (const float*)d_in[20];
    const float* bm2   = (const float*)d_in[21];
    const float* gf    = (const float*)d_in[22];
    const float* bf    = (const float*)d_in[23];

    float *px, *ptmp, *pad;
    u16 *wh, *wl, *hh, *hl, *x12h, *x12l, *q12h, *q12l;
    u16 *vah, *val, *ph_, *pl_, *mh, *ml;
    cudaGetSymbolAddress((void**)&px,   g_x);
    cudaGetSymbolAddress((void**)&ptmp, g_tmp);
    cudaGetSymbolAddress((void**)&pad,  g_adapt);
    cudaGetSymbolAddress((void**)&wh,   g_wh);
    cudaGetSymbolAddress((void**)&wl,   g_wl);
    cudaGetSymbolAddress((void**)&hh,   g_hh);
    cudaGetSymbolAddress((void**)&hl,   g_hl);
    cudaGetSymbolAddress((void**)&x12h, g_x12h);
    cudaGetSymbolAddress((void**)&x12l, g_x12l);
    cudaGetSymbolAddress((void**)&q12h, g_q12h);
    cudaGetSymbolAddress((void**)&q12l, g_q12l);
    cudaGetSymbolAddress((void**)&vah,  g_vah);
    cudaGetSymbolAddress((void**)&val,  g_val);
    cudaGetSymbolAddress((void**)&ph_,  g_ph);
    cudaGetSymbolAddress((void**)&pl_,  g_pl);
    cudaGetSymbolAddress((void**)&mh,   g_mh);
    cudaGetSymbolAddress((void**)&ml,   g_ml);

    const long long QS = (long long)NTOK * 3 * ND;   // q12 branch stride
    const long long XS = (long long)NTOK * ND;       // x12 branch stride
    u16 *q1h = q12h, *q1l = q12l, *q2h = q12h + QS, *q2l = q12l + QS;

    // dynamic smem sizes (bytes)
    const int SM_B128_S2 = 2 * (2*128*40 + 2*32*136) * 2;   // 75776
    const int SM_B64_S3  = 3 * (2*128*40 + 2*32*72)  * 2;   // 89088
    const int SM_FLASH   = (4*128*72 + 2*6*64*72) * 2;      // 184320
    cudaFuncSetAttribute((const void*)mma_gemm<64, false,false,OUT_SPLIT,3>, cudaFuncAttributeMaxDynamicSharedMemorySize, SM_B64_S3);
    cudaFuncSetAttribute((const void*)mma_gemm<64, false,false,OUT_F32,  3>, cudaFuncAttributeMaxDynamicSharedMemorySize, SM_B64_S3);
    cudaFuncSetAttribute((const void*)mma_gemm<64, false,true, OUT_F32,  3>, cudaFuncAttributeMaxDynamicSharedMemorySize, SM_B64_S3);
    cudaFuncSetAttribute((const void*)mma_gemm<128,false,false,OUT_SPLIT,2>, cudaFuncAttributeMaxDynamicSharedMemorySize, SM_B128_S2);
    cudaFuncSetAttribute((const void*)mma_gemm<128,true, false,OUT_SPLIT,2>, cudaFuncAttributeMaxDynamicSharedMemorySize, SM_B128_S2);
    cudaFuncSetAttribute((const void*)flash_kernel, cudaFuncAttributeMaxDynamicSharedMemorySize, SM_FLASH);

    copy_kernel<<<NTOK * ND / 256, 256>>>(x, px, NTOK * ND);

    // pre-split weights, grouped by type (7 launches)
    wsplit_kernel<<<2048, 256>>>(Wp1,   wh + OFF_P1, wl + OFF_P1, (size_t)NL*512*ND);
    wsplit_kernel<<<2048, 256>>>(Wp2,   wh + OFF_P2, wl + OFF_P2, (size_t)NL*512*ND);
    wsplit_kernel<<<4096, 256>>>(Wqkv1, wh + OFF_Q1, wl + OFF_Q1, (size_t)NL*ND*3*ND);
    wsplit_kernel<<<4096, 256>>>(Wqkv2, wh + OFF_Q2, wl + OFF_Q2, (size_t)NL*ND*3*ND);
    wsplit_kernel<<<2048, 256>>>(Wo,    wh + OFF_O,  wl + OFF_O,  (size_t)NL*ND*ND);
    wsplit_kernel<<<4096, 256>>>(Wm1,   wh + OFF_M1, wl + OFF_M1, (size_t)NL*ND*4*ND);
    wsplit_kernel<<<4096, 256>>>(Wm2,   wh + OFF_M2, wl + OFF_M2, (size_t)NL*4*ND*ND);

    for (int l = 0; l < NL; l++) {
        const size_t oP1 = OFF_P1 + (size_t)l*512*ND;
        const size_t oQ1 = OFF_Q1 + (size_t)l*ND*3*ND;
        const size_t oO  = OFF_O  + (size_t)l*ND*ND;
        const size_t oM1 = OFF_M1 + (size_t)l*ND*4*ND;
        const size_t oM2 = OFF_M2 + (size_t)l*4*ND*ND;

        adapt_kernel<<<1, 256>>>(U + (size_t)l * ND * 4, V + (size_t)l * 4 * ND, sigma + l, pad);
        ln_kernel<true, false, true><<<NTOK, 256>>>(px, g1 + l*ND, b1 + l*ND, pad, nullptr, nullptr, hh, hl);

        // x1p & x2p batched (BN=64, 3-stage)
        mma_gemm<64,false,false,OUT_SPLIT,3><<<dim3(16,16,2), 256, SM_B64_S3>>>(
            hh, hl, ND, 0, 512,
            wh+oP1, wl+oP1, ND, 0, (long long)(OFF_P2 - OFF_P1),
            bp1 + l*ND, bp2 + l*ND, nullptr,
            nullptr, x12h, x12l, ND, 0, XS, 512, 1.0f);

        // qkv batched into ONE launch (BN=128, 2-stage)
        mma_gemm<128,false,false,OUT_SPLIT,2><<<dim3(24,16,2), 256, SM_B128_S2>>>(
            x12h, x12l, ND, 0, XS,
            wh+oQ1, wl+oQ1, 3*ND, 0, (long long)(OFF_Q2 - OFF_Q1),
            nullptr, nullptr, nullptr,
            nullptr, q12h, q12l, 3*ND, 0, QS, ND, 1.0f);

        // fused attention
        vavg_t_kernel<<<dim3(16, 32), 256>>>(q1h, q1l, q2h, q2l, vah, val);
        flash_kernel<<<dim3(8, 32), 256, SM_FLASH>>>(q1h, q1l, q2h, q2l, vah, val, ph_, pl_);

        // out proj (BN=64, fp32) + post-LN + residual
        mma_gemm<64,false,false,OUT_F32,3><<<dim3(16,16), 256, SM_B64_S3>>>(
            ph_, pl_, ND, 0, 0, wh+oO, wl+oO, ND, 0, 0,
            bo + l*ND, nullptr, nullptr, ptmp, nullptr, nullptr, ND, 0, 0, ND, 1.0f);
        ln_kernel<false, true, false><<<NTOK, 256>>>(ptmp, gO + l*ND, bO + l*ND, nullptr, px, px, nullptr, nullptr);

        // MLP (Wm1 BN=128)
        ln_kernel<false, false, true><<<NTOK, 256>>>(px, g2 + l*ND, b2 + l*ND, nullptr, nullptr, nullptr, hh, hl);
        mma_gemm<128,true,false,OUT_SPLIT,2><<<dim3(32,16), 256, SM_B128_S2>>>(
            hh, hl, ND, 0, 0, wh+oM1, wl+oM1, 4*ND, 0, 0,
            bm1 + (size_t)l*4*ND, nullptr, nullptr, nullptr, mh, ml, 4*ND, 0, 0, ND, 1.0f);
        mma_gemm<64,false,true,OUT_F32,3><<<dim3(16,16), 256, SM_B64_S3>>>(
            mh, ml, 4*ND, 0, 0, wh+oM2, wl+oM2, ND, 0, 0,
            bm2 + l*ND, nullptr, px, px, nullptr, nullptr, ND, 0, 0, 4*ND, 1.0f);
    }

    ln_kernel<false, false, false><<<NTOK, 256>>>(px, gf, bf, nullptr, nullptr, (float*)d_out, nullptr, nullptr);
}